// round 1
// baseline (speedup 1.0000x reference)
#include <cuda_runtime.h>
#include <cuda_bf16.h>
#include <math.h>

#define B_ 8
#define C_ 256
#define NPIX 4096
#define HID_ 680
#define HEADS_ 8
#define PADW 66

// ---------------- scratch (static device globals; no allocation) ----------------
__device__ __nv_bfloat16 g_xn[B_*C_*NPIX];
__device__ __nv_bfloat16 g_yn[B_*C_*NPIX];
__device__ __nv_bfloat16 g_q [B_*C_*NPIX];
__device__ __nv_bfloat16 g_k [B_*C_*NPIX];
__device__ __nv_bfloat16 g_v [B_*C_*NPIX];
__device__ __nv_bfloat16 g_ov[B_*C_*NPIX];
__device__ float g_x1[B_*C_*NPIX];
__device__ float g_mu2[B_*NPIX];
__device__ float g_istd2[B_*NPIX];
__device__ float g_sumsq_q[B_*C_];
__device__ float g_sumsq_k[B_*C_];
__device__ float g_logits[8*64*32*32];   // [seg][bh][c][d]
__device__ float g_attn[64*32*32];       // [bh][c][d]
__device__ __nv_bfloat16 g_t[B_*2*HID_*NPIX];  // 89 MB
__device__ __nv_bfloat16 g_h[B_*HID_*NPIX];    // 44.6 MB

// ---------------- K1: LayerNorm over channels for x and y ----------------
__global__ void __launch_bounds__(256) k_ln1(
    const float* __restrict__ x, const float* __restrict__ y,
    const float* __restrict__ xw, const float* __restrict__ xb,
    const float* __restrict__ yw, const float* __restrict__ yb)
{
    const int blk = blockIdx.x;         // b*128 + pixel tile
    const int b   = blk >> 7;
    const int pt  = (blk & 127) * 32;
    const int tid = threadIdx.x;
    const int p    = tid & 31;
    const int part = tid >> 5;          // warp id: 8 channel partitions
    const size_t base = (size_t)b*C_*NPIX + pt + p;

    __shared__ float s_s[8][32];
    __shared__ float s_q[8][32];
    __shared__ float s_mu[32];
    __shared__ float s_is[32];

    // ----- x -----
    {
        float s = 0.f, sq = 0.f;
        #pragma unroll 8
        for (int j = 0; j < 32; j++) {
            float v = x[base + (size_t)(part*32 + j)*NPIX];
            s += v; sq += v*v;
        }
        s_s[part][p] = s; s_q[part][p] = sq;
        __syncthreads();
        if (tid < 32) {
            float a = 0.f, c2 = 0.f;
            #pragma unroll
            for (int j = 0; j < 8; j++) { a += s_s[j][tid]; c2 += s_q[j][tid]; }
            float mu = a * (1.f/256.f);
            float var = c2 * (1.f/256.f) - mu*mu;
            s_mu[tid] = mu; s_is[tid] = rsqrtf(var + 1e-5f);
        }
        __syncthreads();
        float mu = s_mu[p], is = s_is[p];
        #pragma unroll 8
        for (int j = 0; j < 32; j++) {
            int c = part*32 + j;
            float v = x[base + (size_t)c*NPIX];
            g_xn[base + (size_t)c*NPIX] = __float2bfloat16((v - mu)*is*xw[c] + xb[c]);
        }
    }
    __syncthreads();
    // ----- y -----
    {
        float s = 0.f, sq = 0.f;
        #pragma unroll 8
        for (int j = 0; j < 32; j++) {
            float v = y[base + (size_t)(part*32 + j)*NPIX];
            s += v; sq += v*v;
        }
        s_s[part][p] = s; s_q[part][p] = sq;
        __syncthreads();
        if (tid < 32) {
            float a = 0.f, c2 = 0.f;
            #pragma unroll
            for (int j = 0; j < 8; j++) { a += s_s[j][tid]; c2 += s_q[j][tid]; }
            float mu = a * (1.f/256.f);
            float var = c2 * (1.f/256.f) - mu*mu;
            s_mu[tid] = mu; s_is[tid] = rsqrtf(var + 1e-5f);
        }
        __syncthreads();
        float mu = s_mu[p], is = s_is[p];
        #pragma unroll 8
        for (int j = 0; j < 32; j++) {
            int c = part*32 + j;
            float v = y[base + (size_t)c*NPIX];
            g_yn[base + (size_t)c*NPIX] = __float2bfloat16((v - mu)*is*yw[c] + yb[c]);
        }
    }
}

// ---------------- K2: depthwise 3x3 QKV + sumsq(q), sumsq(k) ----------------
__global__ void __launch_bounds__(256) k_qkv(const float* __restrict__ dw)
{
    const int blk = blockIdx.x;          // b*256 + c
    const int c   = blk & 255;
    const int tid = threadIdx.x;
    __shared__ __nv_bfloat16 sx[PADW*PADW];
    __shared__ __nv_bfloat16 sy[PADW*PADW];

    const __nv_bfloat16 z = __float2bfloat16(0.f);
    for (int i = tid; i < PADW*PADW; i += 256) { sx[i] = z; sy[i] = z; }
    __syncthreads();
    const size_t pbase = (size_t)blk * NPIX;
    for (int i = tid; i < NPIX; i += 256) {
        int h = i >> 6, w = i & 63;
        sx[(h+1)*PADW + w + 1] = g_xn[pbase + i];
        sy[(h+1)*PADW + w + 1] = g_yn[pbase + i];
    }
    __syncthreads();

    float wq[9], wk[9], wv[9];
    #pragma unroll
    for (int j = 0; j < 9; j++) {
        wq[j] = dw[c*9 + j];
        wk[j] = dw[(256 + c)*9 + j];
        wv[j] = dw[(512 + c)*9 + j];
    }

    float sqq = 0.f, sqk = 0.f;
    for (int i = tid; i < NPIX; i += 256) {
        int h = i >> 6, w = i & 63;
        int s0 = h*PADW + w;   // top-left of 3x3 window in padded coords
        float q = 0.f, k = 0.f, v = 0.f;
        #pragma unroll
        for (int dy = 0; dy < 3; dy++) {
            #pragma unroll
            for (int dx = 0; dx < 3; dx++) {
                float xv = __bfloat162float(sx[s0 + dy*PADW + dx]);
                float yv = __bfloat162float(sy[s0 + dy*PADW + dx]);
                int t = dy*3 + dx;
                q = fmaf(xv, wq[t], q);
                k = fmaf(yv, wk[t], k);
                v = fmaf(yv, wv[t], v);
            }
        }
        g_q[pbase + i] = __float2bfloat16(q);
        g_k[pbase + i] = __float2bfloat16(k);
        g_v[pbase + i] = __float2bfloat16(v);
        sqq += q*q; sqk += k*k;
    }
    // block reduce
    #pragma unroll
    for (int off = 16; off; off >>= 1) {
        sqq += __shfl_down_sync(0xffffffffu, sqq, off);
        sqk += __shfl_down_sync(0xffffffffu, sqk, off);
    }
    __shared__ float rq[8], rk[8];
    if ((tid & 31) == 0) { rq[tid >> 5] = sqq; rk[tid >> 5] = sqk; }
    __syncthreads();
    if (tid == 0) {
        float a = 0.f, bqv = 0.f;
        #pragma unroll
        for (int j = 0; j < 8; j++) { a += rq[j]; bqv += rk[j]; }
        g_sumsq_q[blk] = a;
        g_sumsq_k[blk] = bqv;
    }
}

// ---------------- K3: attention logits (split-K over n) ----------------
__global__ void __launch_bounds__(256) k_attnp()
{
    const int seg = blockIdx.x;   // 0..7  (512 spatial positions each)
    const int bh  = blockIdx.y;   // 0..63
    const int b = bh >> 3, h = bh & 7;
    const int tid = threadIdx.x;
    const int c  = tid >> 3;        // 0..31
    const int dg = (tid & 7) * 4;   // 0,4,...,28

    __shared__ __nv_bfloat16 qs[32*128];
    __shared__ __nv_bfloat16 kt[128*34];   // transposed, padded stride 34

    float a0 = 0.f, a1 = 0.f, a2 = 0.f, a3 = 0.f;
    const size_t base = ((size_t)b*C_ + h*32) * NPIX;

    for (int ch = 0; ch < 4; ch++) {
        int n0 = seg*512 + ch*128;
        __syncthreads();
        for (int i = tid; i < 4096; i += 256) {
            int r = i >> 7, col = i & 127;
            __nv_bfloat16 qv = g_q[base + (size_t)r*NPIX + n0 + col];
            __nv_bfloat16 kv = g_k[base + (size_t)r*NPIX + n0 + col];
            qs[i] = qv;
            kt[col*34 + r] = kv;
        }
        __syncthreads();
        #pragma unroll 4
        for (int j = 0; j < 128; j++) {
            float qv = __bfloat162float(qs[c*128 + j]);
            const __nv_bfloat162* kp = reinterpret_cast<const __nv_bfloat162*>(&kt[j*34 + dg]);
            float2 f0 = __bfloat1622float2(kp[0]);
            float2 f1 = __bfloat1622float2(kp[1]);
            a0 = fmaf(qv, f0.x, a0);
            a1 = fmaf(qv, f0.y, a1);
            a2 = fmaf(qv, f1.x, a2);
            a3 = fmaf(qv, f1.y, a3);
        }
    }
    float* lp = &g_logits[(((size_t)seg*64 + bh)*32 + c)*32 + dg];
    lp[0] = a0; lp[1] = a1; lp[2] = a2; lp[3] = a3;
}

// ---------------- K4: scale + softmax ----------------
__global__ void k_softmax(const float* __restrict__ temp)
{
    const int bh = blockIdx.x;       // 0..63
    const int b = bh >> 3, h = bh & 7;
    const int c = threadIdx.x;       // 0..31
    const float t = temp[h];
    float nq = sqrtf(g_sumsq_q[b*C_ + h*32 + c]);
    float rq = 1.f / fmaxf(nq, 1e-12f);

    float v[32];
    float mx = -1e30f;
    #pragma unroll
    for (int d = 0; d < 32; d++) {
        float s = 0.f;
        #pragma unroll
        for (int sg = 0; sg < 8; sg++)
            s += g_logits[(((size_t)sg*64 + bh)*32 + c)*32 + d];
        float nk = sqrtf(g_sumsq_k[b*C_ + h*32 + d]);
        s *= rq * (1.f / fmaxf(nk, 1e-12f)) * t;
        v[d] = s;
        mx = fmaxf(mx, s);
    }
    float sum = 0.f;
    #pragma unroll
    for (int d = 0; d < 32; d++) { v[d] = expf(v[d] - mx); sum += v[d]; }
    float inv = 1.f / sum;
    #pragma unroll
    for (int d = 0; d < 32; d++)
        g_attn[(size_t)bh*1024 + c*32 + d] = v[d]*inv;
}

// ---------------- K5: out = attn @ v ----------------
__global__ void __launch_bounds__(256) k_av()
{
    const int seg = blockIdx.x;     // 0..7 -> 512 pixels
    const int bh  = blockIdx.y;     // 0..63
    const int b = bh >> 3, h = bh & 7;
    const int tid = threadIdx.x;

    __shared__ float As[32][32];
    __shared__ __nv_bfloat16 vs[32][64];

    for (int i = tid; i < 1024; i += 256)
        As[i >> 5][i & 31] = g_attn[(size_t)bh*1024 + i];

    const size_t vbase = ((size_t)b*C_ + h*32) * NPIX;
    const int p  = tid & 63;
    const int i8 = tid >> 6;    // 0..3 -> 8 output channels each

    for (int s = 0; s < 8; s++) {
        int pb = seg*512 + s*64;
        __syncthreads();
        for (int i = tid; i < 2048; i += 256) {
            int r = i >> 6, cc = i & 63;
            vs[r][cc] = g_v[vbase + (size_t)r*NPIX + pb + cc];
        }
        __syncthreads();
        float acc[8];
        #pragma unroll
        for (int j = 0; j < 8; j++) acc[j] = 0.f;
        #pragma unroll 4
        for (int d = 0; d < 32; d++) {
            float vv = __bfloat162float(vs[d][p]);
            #pragma unroll
            for (int jj = 0; jj < 8; jj++)
                acc[jj] = fmaf(As[i8*8 + jj][d], vv, acc[jj]);
        }
        #pragma unroll
        for (int jj = 0; jj < 8; jj++) {
            int i = i8*8 + jj;
            g_ov[vbase + (size_t)i*NPIX + pb + p] = __float2bfloat16(acc[jj]);
        }
    }
}

// ---------------- K6: LN2 stats on x1 ----------------
__global__ void __launch_bounds__(256) k_ln2stats()
{
    const int blk = blockIdx.x;
    const int b  = blk >> 7;
    const int pt = (blk & 127) * 32;
    const int tid = threadIdx.x;
    const int p = tid & 31;
    const int part = tid >> 5;
    const size_t base = (size_t)b*C_*NPIX + pt + p;

    float s = 0.f, sq = 0.f;
    #pragma unroll 8
    for (int j = 0; j < 32; j++) {
        float v = g_x1[base + (size_t)(part*32 + j)*NPIX];
        s += v; sq += v*v;
    }
    __shared__ float ss[8][32], qq[8][32];
    ss[part][p] = s; qq[part][p] = sq;
    __syncthreads();
    if (tid < 32) {
        float a = 0.f, c2 = 0.f;
        #pragma unroll
        for (int j = 0; j < 8; j++) { a += ss[j][tid]; c2 += qq[j][tid]; }
        float mu = a * (1.f/256.f);
        float var = c2 * (1.f/256.f) - mu*mu;
        g_mu2[b*NPIX + pt + tid]   = mu;
        g_istd2[b*NPIX + pt + tid] = rsqrtf(var + 1e-5f);
    }
}

// ---------------- GEMM (128x128x8 tile, 8x8 microtile, FFMA) ----------------
// MODE 0: x1 = x + Wproj @ ov               (A fp32, B bf16, out fp32)
// MODE 1: t  = Wffn_in @ LN2(x1)            (A fp32, B fp32+LN, out bf16)
// MODE 2: out = x1 + Wffn_out @ h           (A fp32, B bf16, out fp32)
template<int MODE>
__global__ void __launch_bounds__(256) k_gemm(const float* __restrict__ Wt,
                                              const float* __restrict__ aux0,
                                              const float* __restrict__ aux1,
                                              float* __restrict__ outp)
{
    constexpr int O = (MODE == 1) ? 1360 : 256;
    constexpr int K = (MODE == 2) ? 680 : 256;
    const int b  = blockIdx.z;
    const int bn = blockIdx.x * 128;
    const int bm = blockIdx.y * 128;
    const int tid = threadIdx.x;

    __shared__ float As[8][128];
    __shared__ float Bs[8][128];

    const int ar  = tid >> 1;
    const int ac  = (tid & 1) * 4;
    const int brr = tid >> 5;
    const int bcc = (tid & 31) * 4;

    float4 mu4, is4;
    if (MODE == 1) {
        mu4 = *(const float4*)&g_mu2[b*NPIX + bn + bcc];
        is4 = *(const float4*)&g_istd2[b*NPIX + bn + bcc];
    }

    float acc[8][8];
    #pragma unroll
    for (int i = 0; i < 8; i++)
        #pragma unroll
        for (int j = 0; j < 8; j++) acc[i][j] = 0.f;

    const int ty = tid >> 4, tx = tid & 15;
    const int mo = ty*8, no = tx*8;

    for (int k0 = 0; k0 < K; k0 += 8) {
        __syncthreads();
        // A tile: W[bm+ar][k0+ac..+3] -> As[k][m]
        {
            int row = bm + ar;
            float4 a4 = make_float4(0.f, 0.f, 0.f, 0.f);
            if (row < O) a4 = *(const float4*)&Wt[(size_t)row*K + k0 + ac];
            As[ac+0][ar] = a4.x; As[ac+1][ar] = a4.y;
            As[ac+2][ar] = a4.z; As[ac+3][ar] = a4.w;
        }
        // B tile
        {
            int k = k0 + brr;
            if (MODE == 0) {
                const __nv_bfloat162* p2 = reinterpret_cast<const __nv_bfloat162*>(
                    &g_ov[((size_t)b*C_ + k)*NPIX + bn + bcc]);
                float2 f0 = __bfloat1622float2(p2[0]);
                float2 f1 = __bfloat1622float2(p2[1]);
                Bs[brr][bcc+0] = f0.x; Bs[brr][bcc+1] = f0.y;
                Bs[brr][bcc+2] = f1.x; Bs[brr][bcc+3] = f1.y;
            } else if (MODE == 1) {
                float4 v4 = *(const float4*)&g_x1[((size_t)b*C_ + k)*NPIX + bn + bcc];
                float wk = aux0[k], bk = aux1[k];
                Bs[brr][bcc+0] = fmaf((v4.x - mu4.x)*is4.x, wk, bk);
                Bs[brr][bcc+1] = fmaf((v4.y - mu4.y)*is4.y, wk, bk);
                Bs[brr][bcc+2] = fmaf((v4.z - mu4.z)*is4.z, wk, bk);
                Bs[brr][bcc+3] = fmaf((v4.w - mu4.w)*is4.w, wk, bk);
            } else {
                const __nv_bfloat162* p2 = reinterpret_cast<const __nv_bfloat162*>(
                    &g_h[((size_t)b*HID_ + k)*NPIX + bn + bcc]);
                float2 f0 = __bfloat1622float2(p2[0]);
                float2 f1 = __bfloat1622float2(p2[1]);
                Bs[brr][bcc+0] = f0.x; Bs[brr][bcc+1] = f0.y;
                Bs[brr][bcc+2] = f1.x; Bs[brr][bcc+3] = f1.y;
            }
        }
        __syncthreads();
        #pragma unroll
        for (int kk = 0; kk < 8; kk++) {
            float a[8], bb[8];
            *(float4*)&a[0]  = *(const float4*)&As[kk][mo];
            *(float4*)&a[4]  = *(const float4*)&As[kk][mo+4];
            *(float4*)&bb[0] = *(const float4*)&Bs[kk][no];
            *(float4*)&bb[4] = *(const float4*)&Bs[kk][no+4];
            #pragma unroll
            for (int i = 0; i < 8; i++)
                #pragma unroll
                for (int j = 0; j < 8; j++)
                    acc[i][j] = fmaf(a[i], bb[j], acc[i][j]);
        }
    }

    // epilogue
    #pragma unroll
    for (int i = 0; i < 8; i++) {
        int o = bm + mo + i;
        if (MODE == 1) {
            if (o < O) {
                __nv_bfloat162* tp2 = reinterpret_cast<__nv_bfloat162*>(
                    &g_t[((size_t)b*2*HID_ + o)*NPIX + bn + no]);
                #pragma unroll
                for (int j = 0; j < 4; j++)
                    tp2[j] = __floats2bfloat162_rn(acc[i][2*j], acc[i][2*j+1]);
            }
        } else if (MODE == 0) {
            size_t off = ((size_t)b*C_ + o)*NPIX + bn + no;
            float4 r0 = *(const float4*)&aux0[off];
            float4 r1 = *(const float4*)&aux0[off + 4];
            float4 o0 = make_float4(r0.x + acc[i][0], r0.y + acc[i][1],
                                    r0.z + acc[i][2], r0.w + acc[i][3]);
            float4 o1 = make_float4(r1.x + acc[i][4], r1.y + acc[i][5],
                                    r1.z + acc[i][6], r1.w + acc[i][7]);
            *(float4*)&g_x1[off]     = o0;
            *(float4*)&g_x1[off + 4] = o1;
        } else {
            size_t off = ((size_t)b*C_ + o)*NPIX + bn + no;
            float4 r0 = *(const float4*)&g_x1[off];
            float4 r1 = *(const float4*)&g_x1[off + 4];
            float4 o0 = make_float4(r0.x + acc[i][0], r0.y + acc[i][1],
                                    r0.z + acc[i][2], r0.w + acc[i][3]);
            float4 o1 = make_float4(r1.x + acc[i][4], r1.y + acc[i][5],
                                    r1.z + acc[i][6], r1.w + acc[i][7]);
            *(float4*)&outp[off]     = o0;
            *(float4*)&outp[off + 4] = o1;
        }
    }
}

// ---------------- K8: depthwise 3x3 on t, exact GELU gate ----------------
__global__ void __launch_bounds__(256) k_gate(const float* __restrict__ dw)
{
    const int blk = blockIdx.x;         // b*680 + i
    const int b = blk / HID_, i = blk % HID_;
    const int tid = threadIdx.x;
    __shared__ __nv_bfloat16 s1[PADW*PADW];
    __shared__ __nv_bfloat16 s2[PADW*PADW];

    const __nv_bfloat16 z = __float2bfloat16(0.f);
    for (int j = tid; j < PADW*PADW; j += 256) { s1[j] = z; s2[j] = z; }
    __syncthreads();
    const size_t base1 = ((size_t)b*2*HID_ + i) * NPIX;
    const size_t base2 = ((size_t)b*2*HID_ + HID_ + i) * NPIX;
    for (int j = tid; j < NPIX; j += 256) {
        int h = j >> 6, w = j & 63;
        s1[(h+1)*PADW + w + 1] = g_t[base1 + j];
        s2[(h+1)*PADW + w + 1] = g_t[base2 + j];
    }
    __syncthreads();

    float w1[9], w2[9];
    #pragma unroll
    for (int j = 0; j < 9; j++) {
        w1[j] = dw[i*9 + j];
        w2[j] = dw[(HID_ + i)*9 + j];
    }
    const size_t obase = ((size_t)b*HID_ + i) * NPIX;
    for (int j = tid; j < NPIX; j += 256) {
        int h = j >> 6, w = j & 63;
        int s0 = h*PADW + w;
        float a = 0.f, g = 0.f;
        #pragma unroll
        for (int dy = 0; dy < 3; dy++) {
            #pragma unroll
            for (int dx = 0; dx < 3; dx++) {
                int t = dy*3 + dx;
                a = fmaf(__bfloat162float(s1[s0 + dy*PADW + dx]), w1[t], a);
                g = fmaf(__bfloat162float(s2[s0 + dy*PADW + dx]), w2[t], g);
            }
        }
        float ge = 0.5f * a * (1.f + erff(a * 0.70710678118654752f));
        g_h[obase + j] = __float2bfloat16(ge * g);
    }
}

// ---------------- launch ----------------
extern "C" void kernel_launch(void* const* d_in, const int* in_sizes, int n_in,
                              void* d_out, int out_size)
{
    const float* x        = (const float*)d_in[0];
    const float* y        = (const float*)d_in[1];
    const float* ln1x_w   = (const float*)d_in[2];
    const float* ln1x_b   = (const float*)d_in[3];
    const float* ln1y_w   = (const float*)d_in[4];
    const float* ln1y_b   = (const float*)d_in[5];
    const float* ln2_w    = (const float*)d_in[6];
    const float* ln2_b    = (const float*)d_in[7];
    const float* temp     = (const float*)d_in[8];
    const float* qkv_dw   = (const float*)d_in[9];
    const float* proj_w   = (const float*)d_in[10];
    const float* ffn_in_w = (const float*)d_in[11];
    const float* ffn_dw   = (const float*)d_in[12];
    const float* ffn_out_w= (const float*)d_in[13];
    float* out = (float*)d_out;

    k_ln1<<<B_*128, 256>>>(x, y, ln1x_w, ln1x_b, ln1y_w, ln1y_b);
    k_qkv<<<B_*C_, 256>>>(qkv_dw);
    k_attnp<<<dim3(8, 64), 256>>>();
    k_softmax<<<64, 32>>>(temp);
    k_av<<<dim3(8, 64), 256>>>();
    k_gemm<0><<<dim3(32, 2, B_), 256>>>(proj_w, x, nullptr, nullptr);
    k_ln2stats<<<B_*128, 256>>>();
    k_gemm<1><<<dim3(32, 11, B_), 256>>>(ffn_in_w, ln2_w, ln2_b, nullptr);
    k_gate<<<B_*HID_, 256>>>(ffn_dw);
    k_gemm<2><<<dim3(32, 2, B_), 256>>>(ffn_out_w, nullptr, nullptr, out);
}

// round 2
// speedup vs baseline: 2.5915x; 2.5915x over previous
#include <cuda_runtime.h>
#include <cuda_bf16.h>
#include <math.h>

#define B_ 8
#define C_ 256
#define NPIX 4096
#define HID_ 680
#define PADW 66

// ---------------- scratch ----------------
__device__ __nv_bfloat16 g_xn[B_*C_*NPIX];
__device__ __nv_bfloat16 g_yn[B_*C_*NPIX];
__device__ __nv_bfloat16 g_q [B_*C_*NPIX];
__device__ __nv_bfloat16 g_k [B_*C_*NPIX];
__device__ __nv_bfloat16 g_v [B_*C_*NPIX];
__device__ __nv_bfloat16 g_ov[B_*C_*NPIX];
__device__ float g_x1[B_*C_*NPIX];
__device__ float g_sumsq_q[B_*C_];
__device__ float g_sumsq_k[B_*C_];
__device__ float g_logits[8*64*32*32];
__device__ float g_attn[64*32*32];
__device__ __nv_bfloat16 g_t[B_*2*HID_*NPIX];
__device__ __nv_bfloat16 g_h[B_*HID_*NPIX];
// bf16 weights
__device__ __nv_bfloat16 g_wP[256*256];
__device__ __nv_bfloat16 g_wI[1360*256];
__device__ __nv_bfloat16 g_wO[256*680];

// ---------------- weight convert ----------------
__global__ void k_cvtw(const float* __restrict__ p, const float* __restrict__ wi,
                       const float* __restrict__ wo)
{
    const int NP = 256*256, NI = 1360*256, NO = 256*680;
    for (int i = blockIdx.x*256 + threadIdx.x; i < NP+NI+NO; i += gridDim.x*256) {
        if (i < NP) g_wP[i] = __float2bfloat16(p[i]);
        else if (i < NP+NI) g_wI[i-NP] = __float2bfloat16(wi[i-NP]);
        else g_wO[i-NP-NI] = __float2bfloat16(wo[i-NP-NI]);
    }
}

// ---------------- K1: LayerNorm x,y ----------------
__global__ void __launch_bounds__(256) k_ln1(
    const float* __restrict__ x, const float* __restrict__ y,
    const float* __restrict__ xw, const float* __restrict__ xb,
    const float* __restrict__ yw, const float* __restrict__ yb)
{
    const int blk = blockIdx.x;
    const int b   = blk >> 7;
    const int pt  = (blk & 127) * 32;
    const int tid = threadIdx.x;
    const int p    = tid & 31;
    const int part = tid >> 5;
    const size_t base = (size_t)b*C_*NPIX + pt + p;

    __shared__ float s_s[8][32], s_q[8][32], s_mu[32], s_is[32];

    {
        float s = 0.f, sq = 0.f;
        #pragma unroll 8
        for (int j = 0; j < 32; j++) {
            float v = x[base + (size_t)(part*32 + j)*NPIX];
            s += v; sq += v*v;
        }
        s_s[part][p] = s; s_q[part][p] = sq;
        __syncthreads();
        if (tid < 32) {
            float a = 0.f, c2 = 0.f;
            #pragma unroll
            for (int j = 0; j < 8; j++) { a += s_s[j][tid]; c2 += s_q[j][tid]; }
            float mu = a * (1.f/256.f);
            float var = c2 * (1.f/256.f) - mu*mu;
            s_mu[tid] = mu; s_is[tid] = rsqrtf(var + 1e-5f);
        }
        __syncthreads();
        float mu = s_mu[p], is = s_is[p];
        #pragma unroll 8
        for (int j = 0; j < 32; j++) {
            int c = part*32 + j;
            float v = x[base + (size_t)c*NPIX];
            g_xn[base + (size_t)c*NPIX] = __float2bfloat16((v - mu)*is*xw[c] + xb[c]);
        }
    }
    __syncthreads();
    {
        float s = 0.f, sq = 0.f;
        #pragma unroll 8
        for (int j = 0; j < 32; j++) {
            float v = y[base + (size_t)(part*32 + j)*NPIX];
            s += v; sq += v*v;
        }
        s_s[part][p] = s; s_q[part][p] = sq;
        __syncthreads();
        if (tid < 32) {
            float a = 0.f, c2 = 0.f;
            #pragma unroll
            for (int j = 0; j < 8; j++) { a += s_s[j][tid]; c2 += s_q[j][tid]; }
            float mu = a * (1.f/256.f);
            float var = c2 * (1.f/256.f) - mu*mu;
            s_mu[tid] = mu; s_is[tid] = rsqrtf(var + 1e-5f);
        }
        __syncthreads();
        float mu = s_mu[p], is = s_is[p];
        #pragma unroll 8
        for (int j = 0; j < 32; j++) {
            int c = part*32 + j;
            float v = y[base + (size_t)c*NPIX];
            g_yn[base + (size_t)c*NPIX] = __float2bfloat16((v - mu)*is*yw[c] + yb[c]);
        }
    }
}

// ---------------- K2: depthwise QKV + sumsq ----------------
__global__ void __launch_bounds__(256) k_qkv(const float* __restrict__ dw)
{
    const int blk = blockIdx.x;
    const int c   = blk & 255;
    const int tid = threadIdx.x;
    __shared__ __nv_bfloat16 sx[PADW*PADW];
    __shared__ __nv_bfloat16 sy[PADW*PADW];

    const __nv_bfloat16 z = __float2bfloat16(0.f);
    for (int i = tid; i < PADW*PADW; i += 256) { sx[i] = z; sy[i] = z; }
    __syncthreads();
    const size_t pbase = (size_t)blk * NPIX;
    for (int i = tid; i < NPIX; i += 256) {
        int h = i >> 6, w = i & 63;
        sx[(h+1)*PADW + w + 1] = g_xn[pbase + i];
        sy[(h+1)*PADW + w + 1] = g_yn[pbase + i];
    }
    __syncthreads();

    float wq[9], wk[9], wv[9];
    #pragma unroll
    for (int j = 0; j < 9; j++) {
        wq[j] = dw[c*9 + j];
        wk[j] = dw[(256 + c)*9 + j];
        wv[j] = dw[(512 + c)*9 + j];
    }

    float sqq = 0.f, sqk = 0.f;
    for (int i = tid; i < NPIX; i += 256) {
        int h = i >> 6, w = i & 63;
        int s0 = h*PADW + w;
        float q = 0.f, k = 0.f, v = 0.f;
        #pragma unroll
        for (int dy = 0; dy < 3; dy++)
            #pragma unroll
            for (int dx = 0; dx < 3; dx++) {
                float xv = __bfloat162float(sx[s0 + dy*PADW + dx]);
                float yv = __bfloat162float(sy[s0 + dy*PADW + dx]);
                int t = dy*3 + dx;
                q = fmaf(xv, wq[t], q);
                k = fmaf(yv, wk[t], k);
                v = fmaf(yv, wv[t], v);
            }
        g_q[pbase + i] = __float2bfloat16(q);
        g_k[pbase + i] = __float2bfloat16(k);
        g_v[pbase + i] = __float2bfloat16(v);
        sqq += q*q; sqk += k*k;
    }
    #pragma unroll
    for (int off = 16; off; off >>= 1) {
        sqq += __shfl_down_sync(0xffffffffu, sqq, off);
        sqk += __shfl_down_sync(0xffffffffu, sqk, off);
    }
    __shared__ float rq[8], rk[8];
    if ((tid & 31) == 0) { rq[tid >> 5] = sqq; rk[tid >> 5] = sqk; }
    __syncthreads();
    if (tid == 0) {
        float a = 0.f, bqv = 0.f;
        #pragma unroll
        for (int j = 0; j < 8; j++) { a += rq[j]; bqv += rk[j]; }
        g_sumsq_q[blk] = a;
        g_sumsq_k[blk] = bqv;
    }
}

// ---------------- K3: attention logits ----------------
__global__ void __launch_bounds__(256) k_attnp()
{
    const int seg = blockIdx.x;
    const int bh  = blockIdx.y;
    const int b = bh >> 3, h = bh & 7;
    const int tid = threadIdx.x;
    const int c  = tid >> 3;
    const int dg = (tid & 7) * 4;

    __shared__ __nv_bfloat16 qs[32*128];
    __shared__ __nv_bfloat16 kt[128*34];

    float a0 = 0.f, a1 = 0.f, a2 = 0.f, a3 = 0.f;
    const size_t base = ((size_t)b*C_ + h*32) * NPIX;

    for (int ch = 0; ch < 4; ch++) {
        int n0 = seg*512 + ch*128;
        __syncthreads();
        for (int i = tid; i < 4096; i += 256) {
            int r = i >> 7, col = i & 127;
            qs[i] = g_q[base + (size_t)r*NPIX + n0 + col];
            kt[col*34 + r] = g_k[base + (size_t)r*NPIX + n0 + col];
        }
        __syncthreads();
        #pragma unroll 4
        for (int j = 0; j < 128; j++) {
            float qv = __bfloat162float(qs[c*128 + j]);
            const __nv_bfloat162* kp = reinterpret_cast<const __nv_bfloat162*>(&kt[j*34 + dg]);
            float2 f0 = __bfloat1622float2(kp[0]);
            float2 f1 = __bfloat1622float2(kp[1]);
            a0 = fmaf(qv, f0.x, a0);
            a1 = fmaf(qv, f0.y, a1);
            a2 = fmaf(qv, f1.x, a2);
            a3 = fmaf(qv, f1.y, a3);
        }
    }
    float* lp = &g_logits[(((size_t)seg*64 + bh)*32 + c)*32 + dg];
    lp[0] = a0; lp[1] = a1; lp[2] = a2; lp[3] = a3;
}

// ---------------- K4: scale + softmax (256 thr) ----------------
__global__ void __launch_bounds__(256) k_softmax2(const float* __restrict__ temp)
{
    const int bh = blockIdx.x;
    const int b = bh >> 3, h = bh & 7;
    const int tid = threadIdx.x;
    const int c  = tid >> 3;
    const int dg = (tid & 7) * 4;
    const float t = temp[h];
    float nq = sqrtf(g_sumsq_q[b*C_ + h*32 + c]);
    float rq = 1.f / fmaxf(nq, 1e-12f);

    float v[4];
    {
        float4 acc = make_float4(0,0,0,0);
        #pragma unroll
        for (int sg = 0; sg < 8; sg++) {
            float4 l = *(const float4*)&g_logits[(((size_t)sg*64 + bh)*32 + c)*32 + dg];
            acc.x += l.x; acc.y += l.y; acc.z += l.z; acc.w += l.w;
        }
        v[0] = acc.x; v[1] = acc.y; v[2] = acc.z; v[3] = acc.w;
    }
    float mx = -1e30f;
    #pragma unroll
    for (int j = 0; j < 4; j++) {
        float nk = sqrtf(g_sumsq_k[b*C_ + h*32 + dg + j]);
        v[j] *= rq * (1.f / fmaxf(nk, 1e-12f)) * t;
        mx = fmaxf(mx, v[j]);
    }
    #pragma unroll
    for (int m = 1; m < 8; m <<= 1) mx = fmaxf(mx, __shfl_xor_sync(0xffffffffu, mx, m));
    float sum = 0.f;
    #pragma unroll
    for (int j = 0; j < 4; j++) { v[j] = expf(v[j] - mx); sum += v[j]; }
    #pragma unroll
    for (int m = 1; m < 8; m <<= 1) sum += __shfl_xor_sync(0xffffffffu, sum, m);
    float inv = 1.f / sum;
    float4 o = make_float4(v[0]*inv, v[1]*inv, v[2]*inv, v[3]*inv);
    *(float4*)&g_attn[(size_t)bh*1024 + c*32 + dg] = o;
}

// ---------------- K5: out = attn @ v ----------------
__global__ void __launch_bounds__(256) k_av()
{
    const int seg = blockIdx.x;
    const int bh  = blockIdx.y;
    const int b = bh >> 3, h = bh & 7;
    const int tid = threadIdx.x;

    __shared__ float As[32][32];
    __shared__ __nv_bfloat16 vs[32][64];

    for (int i = tid; i < 1024; i += 256)
        As[i >> 5][i & 31] = g_attn[(size_t)bh*1024 + i];

    const size_t vbase = ((size_t)b*C_ + h*32) * NPIX;
    const int p  = tid & 63;
    const int i8 = tid >> 6;

    for (int s = 0; s < 8; s++) {
        int pb = seg*512 + s*64;
        __syncthreads();
        for (int i = tid; i < 2048; i += 256) {
            int r = i >> 6, cc = i & 63;
            vs[r][cc] = g_v[vbase + (size_t)r*NPIX + pb + cc];
        }
        __syncthreads();
        float acc[8];
        #pragma unroll
        for (int j = 0; j < 8; j++) acc[j] = 0.f;
        #pragma unroll 4
        for (int d = 0; d < 32; d++) {
            float vv = __bfloat162float(vs[d][p]);
            #pragma unroll
            for (int jj = 0; jj < 8; jj++)
                acc[jj] = fmaf(As[i8*8 + jj][d], vv, acc[jj]);
        }
        #pragma unroll
        for (int jj = 0; jj < 8; jj++) {
            int i = i8*8 + jj;
            g_ov[vbase + (size_t)i*NPIX + pb + p] = __float2bfloat16(acc[jj]);
        }
    }
}

// ---------------- K6: LN2 -> bf16 into g_xn ----------------
__global__ void __launch_bounds__(256) k_ln2(const float* __restrict__ w,
                                             const float* __restrict__ bia)
{
    const int blk = blockIdx.x;
    const int b  = blk >> 7;
    const int pt = (blk & 127) * 32;
    const int tid = threadIdx.x;
    const int p = tid & 31;
    const int part = tid >> 5;
    const size_t base = (size_t)b*C_*NPIX + pt + p;

    __shared__ float ss[8][32], qq[8][32], s_mu[32], s_is[32];
    float s = 0.f, sq = 0.f;
    #pragma unroll 8
    for (int j = 0; j < 32; j++) {
        float v = g_x1[base + (size_t)(part*32 + j)*NPIX];
        s += v; sq += v*v;
    }
    ss[part][p] = s; qq[part][p] = sq;
    __syncthreads();
    if (tid < 32) {
        float a = 0.f, c2 = 0.f;
        #pragma unroll
        for (int j = 0; j < 8; j++) { a += ss[j][tid]; c2 += qq[j][tid]; }
        float mu = a * (1.f/256.f);
        float var = c2 * (1.f/256.f) - mu*mu;
        s_mu[tid] = mu; s_is[tid] = rsqrtf(var + 1e-5f);
    }
    __syncthreads();
    float mu = s_mu[p], is = s_is[p];
    #pragma unroll 8
    for (int j = 0; j < 32; j++) {
        int c = part*32 + j;
        float v = g_x1[base + (size_t)c*NPIX];
        g_xn[base + (size_t)c*NPIX] = __float2bfloat16((v - mu)*is*w[c] + bia[c]);
    }
}

// ---------------- tensor-core GEMM ----------------
// D[o][n] = sum_k W[o][k] * Act[k][n]   (+ epilogue per MODE)
#define MMA16816(d, a, b0, b1) \
    asm volatile("mma.sync.aligned.m16n8k16.row.col.f32.bf16.bf16.f32 " \
        "{%0,%1,%2,%3},{%4,%5,%6,%7},{%8,%9},{%0,%1,%2,%3};" \
        : "+f"(d[0]),"+f"(d[1]),"+f"(d[2]),"+f"(d[3]) \
        : "r"(a[0]),"r"(a[1]),"r"(a[2]),"r"(a[3]),"r"(b0),"r"(b1))

#define LDSM4(r0,r1,r2,r3,addr) \
    asm volatile("ldmatrix.sync.aligned.m8n8.x4.shared.b16 {%0,%1,%2,%3},[%4];" \
        : "=r"(r0),"=r"(r1),"=r"(r2),"=r"(r3) : "r"(addr))

#define LDSM4T(r0,r1,r2,r3,addr) \
    asm volatile("ldmatrix.sync.aligned.m8n8.x4.trans.shared.b16 {%0,%1,%2,%3},[%4];" \
        : "=r"(r0),"=r"(r1),"=r"(r2),"=r"(r3) : "r"(addr))

#define CP16(dst, src) \
    asm volatile("cp.async.cg.shared.global [%0], [%1], 16;" :: "r"(dst), "l"(src))

template<int MODE>
__global__ void __launch_bounds__(256) k_mma(const __nv_bfloat16* __restrict__ Wb,
                                             const __nv_bfloat16* __restrict__ Act,
                                             const float* __restrict__ res,
                                             float* __restrict__ outp)
{
    constexpr int O = (MODE == 1) ? 1360 : 256;
    constexpr int K = (MODE == 2) ? 680 : 256;
    constexpr int NC = (K + 31) / 32;
    constexpr int ASZ = 128*40;   // elems per A stage
    constexpr int BSZ = 32*136;

    const int b  = blockIdx.z;
    const int bn = blockIdx.x * 128;
    const int bm = blockIdx.y * 128;
    const int tid = threadIdx.x, lane = tid & 31, warp = tid >> 5;
    const int wm = warp >> 1, wn = warp & 1;
    const int gid = lane >> 2, tg = lane & 3;

    __shared__ __align__(16) __nv_bfloat16 sA[2][ASZ];
    __shared__ __align__(16) __nv_bfloat16 sB[2][BSZ];
    const unsigned sAu = (unsigned)__cvta_generic_to_shared(&sA[0][0]);
    const unsigned sBu = (unsigned)__cvta_generic_to_shared(&sB[0][0]);

    // load-thread indices
    const int ar = tid >> 1, ac = (tid & 1) * 16;
    const int bk = tid >> 3, bn8 = (tid & 7) * 16;
    int arow = bm + ar; if (arow > O-1) arow = O-1;
    const __nv_bfloat16* Arow = Wb + (size_t)arow * K;
    const __nv_bfloat16* Bbase = Act + (size_t)b * K * NPIX + bn;

    float acc[2][8][4];
    #pragma unroll
    for (int i = 0; i < 2; i++)
        #pragma unroll
        for (int j = 0; j < 8; j++)
            #pragma unroll
            for (int q = 0; q < 4; q++) acc[i][j][q] = 0.f;

    auto load_chunk = [&](int c, int buf) {
        const int k0 = c * 32;
        #pragma unroll
        for (int j = 0; j < 2; j++) {
            int ko = ac + j*8;
            unsigned dst = sAu + (buf*ASZ + ar*40 + ko) * 2;
            if (k0 + ko < K) { CP16(dst, Arow + k0 + ko); }
            else *(float4*)(&sA[buf][ar*40 + ko]) = make_float4(0,0,0,0);
        }
        #pragma unroll
        for (int j = 0; j < 2; j++) {
            int no = bn8 + j*8;
            unsigned dst = sBu + (buf*BSZ + bk*136 + no) * 2;
            if (k0 + bk < K) { CP16(dst, Bbase + (size_t)(k0 + bk)*NPIX + no); }
            else *(float4*)(&sB[buf][bk*136 + no]) = make_float4(0,0,0,0);
        }
        asm volatile("cp.async.commit_group;" ::);
    };

    load_chunk(0, 0);

    for (int c = 0; c < NC; c++) {
        const int buf = c & 1;
        if (c + 1 < NC) {
            load_chunk(c + 1, (c + 1) & 1);
            asm volatile("cp.async.wait_group 1;" ::);
        } else {
            asm volatile("cp.async.wait_group 0;" ::);
        }
        __syncthreads();

        #pragma unroll
        for (int kt = 0; kt < 2; kt++) {
            unsigned a[2][4];
            #pragma unroll
            for (int mt = 0; mt < 2; mt++) {
                unsigned addr = sAu + (buf*ASZ +
                    (wm*32 + mt*16 + (lane & 15))*40 + kt*16 + (lane >> 4)*8) * 2;
                LDSM4(a[mt][0], a[mt][1], a[mt][2], a[mt][3], addr);
            }
            #pragma unroll
            for (int ntp = 0; ntp < 4; ntp++) {
                unsigned b0, b1, b2, b3;
                unsigned addr = sBu + (buf*BSZ +
                    (kt*16 + (lane & 7) + ((lane >> 3) & 1)*8)*136 +
                    wn*64 + ntp*16 + (lane >> 4)*8) * 2;
                LDSM4T(b0, b1, b2, b3, addr);
                MMA16816(acc[0][2*ntp],   a[0], b0, b1);
                MMA16816(acc[1][2*ntp],   a[1], b0, b1);
                MMA16816(acc[0][2*ntp+1], a[0], b2, b3);
                MMA16816(acc[1][2*ntp+1], a[1], b2, b3);
            }
        }
        __syncthreads();
    }

    // epilogue
    #pragma unroll
    for (int mt = 0; mt < 2; mt++) {
        #pragma unroll
        for (int nt = 0; nt < 8; nt++) {
            int row = bm + wm*32 + mt*16 + gid;
            int col = bn + wn*64 + nt*8 + tg*2;
            float* a4 = acc[mt][nt];
            if (MODE == 0) {
                size_t o0 = ((size_t)b*256 + row)*NPIX + col;
                size_t o1 = o0 + (size_t)8*NPIX;
                float2 r0 = *(const float2*)&res[o0];
                float2 r1 = *(const float2*)&res[o1];
                *(float2*)&g_x1[o0] = make_float2(r0.x + a4[0], r0.y + a4[1]);
                *(float2*)&g_x1[o1] = make_float2(r1.x + a4[2], r1.y + a4[3]);
            } else if (MODE == 1) {
                if (row < 1360) {
                    size_t o0 = ((size_t)b*1360 + row)*NPIX + col;
                    *(__nv_bfloat162*)&g_t[o0] = __floats2bfloat162_rn(a4[0], a4[1]);
                }
                if (row + 8 < 1360) {
                    size_t o1 = ((size_t)b*1360 + row + 8)*NPIX + col;
                    *(__nv_bfloat162*)&g_t[o1] = __floats2bfloat162_rn(a4[2], a4[3]);
                }
            } else {
                size_t o0 = ((size_t)b*256 + row)*NPIX + col;
                size_t o1 = o0 + (size_t)8*NPIX;
                float2 r0 = *(const float2*)&g_x1[o0];
                float2 r1 = *(const float2*)&g_x1[o1];
                *(float2*)&outp[o0] = make_float2(r0.x + a4[0], r0.y + a4[1]);
                *(float2*)&outp[o1] = make_float2(r1.x + a4[2], r1.y + a4[3]);
            }
        }
    }
}

// ---------------- K8: depthwise + GELU gate ----------------
__global__ void __launch_bounds__(256) k_gate(const float* __restrict__ dw)
{
    const int blk = blockIdx.x;
    const int b = blk / HID_, i = blk % HID_;
    const int tid = threadIdx.x;
    __shared__ __nv_bfloat16 s1[PADW*PADW];
    __shared__ __nv_bfloat16 s2[PADW*PADW];

    const __nv_bfloat16 z = __float2bfloat16(0.f);
    for (int j = tid; j < PADW*PADW; j += 256) { s1[j] = z; s2[j] = z; }
    __syncthreads();
    const size_t base1 = ((size_t)b*2*HID_ + i) * NPIX;
    const size_t base2 = ((size_t)b*2*HID_ + HID_ + i) * NPIX;
    for (int j = tid; j < NPIX; j += 256) {
        int h = j >> 6, w = j & 63;
        s1[(h+1)*PADW + w + 1] = g_t[base1 + j];
        s2[(h+1)*PADW + w + 1] = g_t[base2 + j];
    }
    __syncthreads();

    float w1[9], w2[9];
    #pragma unroll
    for (int j = 0; j < 9; j++) {
        w1[j] = dw[i*9 + j];
        w2[j] = dw[(HID_ + i)*9 + j];
    }
    const size_t obase = ((size_t)b*HID_ + i) * NPIX;
    for (int j = tid; j < NPIX; j += 256) {
        int h = j >> 6, w = j & 63;
        int s0 = h*PADW + w;
        float a = 0.f, g = 0.f;
        #pragma unroll
        for (int dy = 0; dy < 3; dy++)
            #pragma unroll
            for (int dx = 0; dx < 3; dx++) {
                int t = dy*3 + dx;
                a = fmaf(__bfloat162float(s1[s0 + dy*PADW + dx]), w1[t], a);
                g = fmaf(__bfloat162float(s2[s0 + dy*PADW + dx]), w2[t], g);
            }
        float ge = 0.5f * a * (1.f + erff(a * 0.70710678118654752f));
        g_h[obase + j] = __float2bfloat16(ge * g);
    }
}

// ---------------- launch ----------------
extern "C" void kernel_launch(void* const* d_in, const int* in_sizes, int n_in,
                              void* d_out, int out_size)
{
    const float* x        = (const float*)d_in[0];
    const float* y        = (const float*)d_in[1];
    const float* ln1x_w   = (const float*)d_in[2];
    const float* ln1x_b   = (const float*)d_in[3];
    const float* ln1y_w   = (const float*)d_in[4];
    const float* ln1y_b   = (const float*)d_in[5];
    const float* ln2_w    = (const float*)d_in[6];
    const float* ln2_b    = (const float*)d_in[7];
    const float* temp     = (const float*)d_in[8];
    const float* qkv_dw   = (const float*)d_in[9];
    const float* proj_w   = (const float*)d_in[10];
    const float* ffn_in_w = (const float*)d_in[11];
    const float* ffn_dw   = (const float*)d_in[12];
    const float* ffn_out_w= (const float*)d_in[13];
    float* out = (float*)d_out;

    __nv_bfloat16 *wP, *wI, *wO;
    cudaGetSymbolAddress((void**)&wP, g_wP);
    cudaGetSymbolAddress((void**)&wI, g_wI);
    cudaGetSymbolAddress((void**)&wO, g_wO);
    __nv_bfloat16 *ov, *xn, *hh;
    cudaGetSymbolAddress((void**)&ov, g_ov);
    cudaGetSymbolAddress((void**)&xn, g_xn);
    cudaGetSymbolAddress((void**)&hh, g_h);

    k_cvtw<<<576, 256>>>(proj_w, ffn_in_w, ffn_out_w);
    k_ln1<<<B_*128, 256>>>(x, y, ln1x_w, ln1x_b, ln1y_w, ln1y_b);
    k_qkv<<<B_*C_, 256>>>(qkv_dw);
    k_attnp<<<dim3(8, 64), 256>>>();
    k_softmax2<<<64, 256>>>(temp);
    k_av<<<dim3(8, 64), 256>>>();
    k_mma<0><<<dim3(32, 2, B_), 256>>>(wP, ov, x, nullptr);
    k_ln2<<<B_*128, 256>>>(ln2_w, ln2_b);
    k_mma<1><<<dim3(32, 11, B_), 256>>>(wI, xn, nullptr, nullptr);
    k_gate<<<B_*HID_, 256>>>(ffn_dw);
    k_mma<2><<<dim3(32, 2, B_), 256>>>(wO, hh, nullptr, out);
}

// round 3
// speedup vs baseline: 2.9126x; 1.1239x over previous
#include <cuda_runtime.h>
#include <cuda_bf16.h>
#include <math.h>

#define B_ 8
#define C_ 256
#define NPIX 4096
#define HID_ 680
#define PADW 66

// ---------------- scratch ----------------
__device__ __nv_bfloat16 g_xn[B_*C_*NPIX];
__device__ __nv_bfloat16 g_yn[B_*C_*NPIX];
__device__ __nv_bfloat16 g_q [B_*C_*NPIX];
__device__ __nv_bfloat16 g_k [B_*C_*NPIX];
__device__ __nv_bfloat16 g_v [B_*C_*NPIX];
__device__ __nv_bfloat16 g_ov[B_*C_*NPIX];
__device__ float g_x1[B_*C_*NPIX];
__device__ float g_sumsq_q[B_*C_];
__device__ float g_sumsq_k[B_*C_];
__device__ __nv_bfloat16 g_attnb[64*1024];   // [bh][c][d] bf16
__device__ __nv_bfloat16 g_t[B_*2*HID_*NPIX];
__device__ __nv_bfloat16 g_h[B_*HID_*NPIX];
// bf16 weights
__device__ __nv_bfloat16 g_wP[256*256];
__device__ __nv_bfloat16 g_wI[1360*256];
__device__ __nv_bfloat16 g_wO[256*680];

// ---------------- mma helpers ----------------
#define MMA16816(d, a, b0, b1) \
    asm volatile("mma.sync.aligned.m16n8k16.row.col.f32.bf16.bf16.f32 " \
        "{%0,%1,%2,%3},{%4,%5,%6,%7},{%8,%9},{%0,%1,%2,%3};" \
        : "+f"(d[0]),"+f"(d[1]),"+f"(d[2]),"+f"(d[3]) \
        : "r"(a[0]),"r"(a[1]),"r"(a[2]),"r"(a[3]),"r"(b0),"r"(b1))

#define LDSM4(r0,r1,r2,r3,addr) \
    asm volatile("ldmatrix.sync.aligned.m8n8.x4.shared.b16 {%0,%1,%2,%3},[%4];" \
        : "=r"(r0),"=r"(r1),"=r"(r2),"=r"(r3) : "r"(addr))

#define LDSM4T(r0,r1,r2,r3,addr) \
    asm volatile("ldmatrix.sync.aligned.m8n8.x4.trans.shared.b16 {%0,%1,%2,%3},[%4];" \
        : "=r"(r0),"=r"(r1),"=r"(r2),"=r"(r3) : "r"(addr))

#define CP16(dst, src) \
    asm volatile("cp.async.cg.shared.global [%0], [%1], 16;" :: "r"(dst), "l"(src))

// ---------------- weight convert ----------------
__global__ void k_cvtw(const float* __restrict__ p, const float* __restrict__ wi,
                       const float* __restrict__ wo)
{
    const int NP = 256*256, NI = 1360*256, NO = 256*680;
    for (int i = blockIdx.x*256 + threadIdx.x; i < NP+NI+NO; i += gridDim.x*256) {
        if (i < NP) g_wP[i] = __float2bfloat16(p[i]);
        else if (i < NP+NI) g_wI[i-NP] = __float2bfloat16(wi[i-NP]);
        else g_wO[i-NP-NI] = __float2bfloat16(wo[i-NP-NI]);
    }
}

// ---------------- K1: LayerNorm x,y ----------------
__global__ void __launch_bounds__(256) k_ln1(
    const float* __restrict__ x, const float* __restrict__ y,
    const float* __restrict__ xw, const float* __restrict__ xb,
    const float* __restrict__ yw, const float* __restrict__ yb)
{
    const int blk = blockIdx.x;
    const int b   = blk >> 7;
    const int pt  = (blk & 127) * 32;
    const int tid = threadIdx.x;
    const int p    = tid & 31;
    const int part = tid >> 5;
    const size_t base = (size_t)b*C_*NPIX + pt + p;

    __shared__ float s_s[8][32], s_q[8][32], s_mu[32], s_is[32];

    {
        float s = 0.f, sq = 0.f;
        #pragma unroll 8
        for (int j = 0; j < 32; j++) {
            float v = x[base + (size_t)(part*32 + j)*NPIX];
            s += v; sq += v*v;
        }
        s_s[part][p] = s; s_q[part][p] = sq;
        __syncthreads();
        if (tid < 32) {
            float a = 0.f, c2 = 0.f;
            #pragma unroll
            for (int j = 0; j < 8; j++) { a += s_s[j][tid]; c2 += s_q[j][tid]; }
            float mu = a * (1.f/256.f);
            float var = c2 * (1.f/256.f) - mu*mu;
            s_mu[tid] = mu; s_is[tid] = rsqrtf(var + 1e-5f);
        }
        __syncthreads();
        float mu = s_mu[p], is = s_is[p];
        #pragma unroll 8
        for (int j = 0; j < 32; j++) {
            int c = part*32 + j;
            float v = x[base + (size_t)c*NPIX];
            g_xn[base + (size_t)c*NPIX] = __float2bfloat16((v - mu)*is*xw[c] + xb[c]);
        }
    }
    __syncthreads();
    {
        float s = 0.f, sq = 0.f;
        #pragma unroll 8
        for (int j = 0; j < 32; j++) {
            float v = y[base + (size_t)(part*32 + j)*NPIX];
            s += v; sq += v*v;
        }
        s_s[part][p] = s; s_q[part][p] = sq;
        __syncthreads();
        if (tid < 32) {
            float a = 0.f, c2 = 0.f;
            #pragma unroll
            for (int j = 0; j < 8; j++) { a += s_s[j][tid]; c2 += s_q[j][tid]; }
            float mu = a * (1.f/256.f);
            float var = c2 * (1.f/256.f) - mu*mu;
            s_mu[tid] = mu; s_is[tid] = rsqrtf(var + 1e-5f);
        }
        __syncthreads();
        float mu = s_mu[p], is = s_is[p];
        #pragma unroll 8
        for (int j = 0; j < 32; j++) {
            int c = part*32 + j;
            float v = y[base + (size_t)c*NPIX];
            g_yn[base + (size_t)c*NPIX] = __float2bfloat16((v - mu)*is*yw[c] + yb[c]);
        }
    }
}

// ---------------- K2: depthwise QKV + sumsq ----------------
__global__ void __launch_bounds__(256) k_qkv(const float* __restrict__ dw)
{
    const int blk = blockIdx.x;
    const int c   = blk & 255;
    const int tid = threadIdx.x;
    __shared__ __nv_bfloat16 sx[PADW*PADW];
    __shared__ __nv_bfloat16 sy[PADW*PADW];

    const __nv_bfloat16 z = __float2bfloat16(0.f);
    for (int i = tid; i < PADW*PADW; i += 256) { sx[i] = z; sy[i] = z; }
    __syncthreads();
    const size_t pbase = (size_t)blk * NPIX;
    for (int i = tid; i < NPIX; i += 256) {
        int h = i >> 6, w = i & 63;
        sx[(h+1)*PADW + w + 1] = g_xn[pbase + i];
        sy[(h+1)*PADW + w + 1] = g_yn[pbase + i];
    }
    __syncthreads();

    float wq[9], wk[9], wv[9];
    #pragma unroll
    for (int j = 0; j < 9; j++) {
        wq[j] = dw[c*9 + j];
        wk[j] = dw[(256 + c)*9 + j];
        wv[j] = dw[(512 + c)*9 + j];
    }

    float sqq = 0.f, sqk = 0.f;
    for (int i = tid; i < NPIX; i += 256) {
        int h = i >> 6, w = i & 63;
        int s0 = h*PADW + w;
        float q = 0.f, k = 0.f, v = 0.f;
        #pragma unroll
        for (int dy = 0; dy < 3; dy++)
            #pragma unroll
            for (int dx = 0; dx < 3; dx++) {
                float xv = __bfloat162float(sx[s0 + dy*PADW + dx]);
                float yv = __bfloat162float(sy[s0 + dy*PADW + dx]);
                int t = dy*3 + dx;
                q = fmaf(xv, wq[t], q);
                k = fmaf(yv, wk[t], k);
                v = fmaf(yv, wv[t], v);
            }
        g_q[pbase + i] = __float2bfloat16(q);
        g_k[pbase + i] = __float2bfloat16(k);
        g_v[pbase + i] = __float2bfloat16(v);
        sqq += q*q; sqk += k*k;
    }
    #pragma unroll
    for (int off = 16; off; off >>= 1) {
        sqq += __shfl_down_sync(0xffffffffu, sqq, off);
        sqk += __shfl_down_sync(0xffffffffu, sqk, off);
    }
    __shared__ float rq[8], rk[8];
    if ((tid & 31) == 0) { rq[tid >> 5] = sqq; rk[tid >> 5] = sqk; }
    __syncthreads();
    if (tid == 0) {
        float a = 0.f, bqv = 0.f;
        #pragma unroll
        for (int j = 0; j < 8; j++) { a += rq[j]; bqv += rk[j]; }
        g_sumsq_q[blk] = a;
        g_sumsq_k[blk] = bqv;
    }
}

// ---------------- K3: fused QK^T (mma) + softmax ----------------
// one block per (b,h); S = Q K^T over K=4096, softmax, write bf16 attn
__global__ void __launch_bounds__(256) k_qks(const float* __restrict__ temp)
{
    const int bh = blockIdx.x;
    const int b = bh >> 3, h = bh & 7;
    const int tid = threadIdx.x, lane = tid & 31, warp = tid >> 5;
    const int gid = lane >> 2, tg = lane & 3;

    // stage: 32 rows x 136 (pad) per buffer
    __shared__ __align__(16) __nv_bfloat16 sQ[2][32*136];
    __shared__ __align__(16) __nv_bfloat16 sK[2][32*136];
    const unsigned sQu = (unsigned)__cvta_generic_to_shared(&sQ[0][0]);
    const unsigned sKu = (unsigned)__cvta_generic_to_shared(&sK[0][0]);

    const size_t base = ((size_t)b*C_ + h*32) * NPIX;
    const int r  = tid >> 3;
    const int cg = (tid & 7) * 16;

    auto prefetch = [&](int c, int buf) {
        const int n0 = c * 128;
        const __nv_bfloat16* qp = g_q + base + (size_t)r*NPIX + n0 + cg;
        const __nv_bfloat16* kp = g_k + base + (size_t)r*NPIX + n0 + cg;
        unsigned dq = sQu + (buf*32*136 + r*136 + cg) * 2;
        unsigned dk = sKu + (buf*32*136 + r*136 + cg) * 2;
        CP16(dq,      qp);
        CP16(dq + 16, qp + 8);
        CP16(dk,      kp);
        CP16(dk + 16, kp + 8);
        asm volatile("cp.async.commit_group;" ::);
    };

    float acc[2][4][4];
    #pragma unroll
    for (int i = 0; i < 2; i++)
        #pragma unroll
        for (int j = 0; j < 4; j++)
            #pragma unroll
            for (int q = 0; q < 4; q++) acc[i][j][q] = 0.f;

    prefetch(0, 0);

    for (int c = 0; c < 32; c++) {
        const int buf = c & 1;
        if (c + 1 < 32) {
            prefetch(c + 1, buf ^ 1);
            asm volatile("cp.async.wait_group 1;" ::);
        } else {
            asm volatile("cp.async.wait_group 0;" ::);
        }
        __syncthreads();

        const int col = warp*16 + (lane >> 4)*8;
        unsigned a[2][4];
        #pragma unroll
        for (int mt = 0; mt < 2; mt++) {
            unsigned addr = sQu + (buf*32*136 + (mt*16 + (lane & 15))*136 + col) * 2;
            LDSM4(a[mt][0], a[mt][1], a[mt][2], a[mt][3], addr);
        }
        #pragma unroll
        for (int nt = 0; nt < 2; nt++) {
            unsigned r0, r1, r2, r3;
            unsigned addr = sKu + (buf*32*136 + (nt*16 + (lane & 15))*136 + col) * 2;
            LDSM4(r0, r1, r2, r3, addr);
            MMA16816(acc[0][nt*2],   a[0], r0, r2);
            MMA16816(acc[1][nt*2],   a[1], r0, r2);
            MMA16816(acc[0][nt*2+1], a[0], r1, r3);
            MMA16816(acc[1][nt*2+1], a[1], r1, r3);
        }
        __syncthreads();
    }

    // cross-warp reduction: stage[w][c][d] with stride 33 (8448 floats = sQ+sK area)
    float* stage = reinterpret_cast<float*>(&sQ[0][0]);
    #pragma unroll
    for (int mt = 0; mt < 2; mt++)
        #pragma unroll
        for (int j = 0; j < 4; j++) {
            int c0 = mt*16 + gid, d0 = j*8 + tg*2;
            stage[warp*1056 + c0*33 + d0]       = acc[mt][j][0];
            stage[warp*1056 + c0*33 + d0 + 1]   = acc[mt][j][1];
            stage[warp*1056 + (c0+8)*33 + d0]   = acc[mt][j][2];
            stage[warp*1056 + (c0+8)*33 + d0+1] = acc[mt][j][3];
        }
    __syncthreads();

    const int cc = tid >> 3;
    const int dg = (tid & 7) * 4;
    float v[4] = {0.f, 0.f, 0.f, 0.f};
    #pragma unroll
    for (int w = 0; w < 8; w++)
        #pragma unroll
        for (int j = 0; j < 4; j++)
            v[j] += stage[w*1056 + cc*33 + dg + j];

    const float t = temp[h];
    float nq = sqrtf(g_sumsq_q[b*C_ + h*32 + cc]);
    float rq = 1.f / fmaxf(nq, 1e-12f);
    float mx = -1e30f;
    #pragma unroll
    for (int j = 0; j < 4; j++) {
        float nk = sqrtf(g_sumsq_k[b*C_ + h*32 + dg + j]);
        v[j] *= rq * (1.f / fmaxf(nk, 1e-12f)) * t;
        mx = fmaxf(mx, v[j]);
    }
    #pragma unroll
    for (int m = 1; m < 8; m <<= 1) mx = fmaxf(mx, __shfl_xor_sync(0xffffffffu, mx, m));
    float sum = 0.f;
    #pragma unroll
    for (int j = 0; j < 4; j++) { v[j] = expf(v[j] - mx); sum += v[j]; }
    #pragma unroll
    for (int m = 1; m < 8; m <<= 1) sum += __shfl_xor_sync(0xffffffffu, sum, m);
    float inv = 1.f / sum;
    __nv_bfloat162* op = reinterpret_cast<__nv_bfloat162*>(&g_attnb[(size_t)bh*1024 + cc*32 + dg]);
    op[0] = __floats2bfloat162_rn(v[0]*inv, v[1]*inv);
    op[1] = __floats2bfloat162_rn(v[2]*inv, v[3]*inv);
}

// ---------------- K5: out = attn @ v (mma) ----------------
__global__ void __launch_bounds__(256) k_av2()
{
    const int seg = blockIdx.x;     // 512 pixels
    const int bh  = blockIdx.y;
    const int b = bh >> 3, h = bh & 7;
    const int tid = threadIdx.x, lane = tid & 31, warp = tid >> 5;
    const int gid = lane >> 2, tg = lane & 3;

    __shared__ __align__(16) __nv_bfloat16 sA[32*40];
    __shared__ __align__(16) __nv_bfloat16 sV[32*520];
    const unsigned sAu = (unsigned)__cvta_generic_to_shared(&sA[0]);
    const unsigned sVu = (unsigned)__cvta_generic_to_shared(&sV[0]);

    // load attn 32x32
    {
        int c0 = tid >> 3, d0 = (tid & 7) * 4;
        const __nv_bfloat162* ap = reinterpret_cast<const __nv_bfloat162*>(
            &g_attnb[(size_t)bh*1024 + c0*32 + d0]);
        __nv_bfloat162* sp = reinterpret_cast<__nv_bfloat162*>(&sA[c0*40 + d0]);
        sp[0] = ap[0]; sp[1] = ap[1];
    }
    // load V 32x512
    const size_t vbase = ((size_t)b*C_ + h*32) * NPIX;
    const int pb0 = seg * 512;
    {
        int r = tid >> 3, cg = (tid & 7) * 64;
        #pragma unroll
        for (int j = 0; j < 8; j++)
            *(float4*)&sV[r*520 + cg + j*8] =
                *(const float4*)&g_v[vbase + (size_t)r*NPIX + pb0 + cg + j*8];
    }
    __syncthreads();

    float acc[2][8][4];
    #pragma unroll
    for (int i = 0; i < 2; i++)
        #pragma unroll
        for (int j = 0; j < 8; j++)
            #pragma unroll
            for (int q = 0; q < 4; q++) acc[i][j][q] = 0.f;

    #pragma unroll
    for (int kt = 0; kt < 2; kt++) {
        unsigned a[2][4];
        #pragma unroll
        for (int mt = 0; mt < 2; mt++) {
            unsigned addr = sAu + ((mt*16 + (lane & 15))*40 + kt*16 + (lane >> 4)*8) * 2;
            LDSM4(a[mt][0], a[mt][1], a[mt][2], a[mt][3], addr);
        }
        #pragma unroll
        for (int ntp = 0; ntp < 4; ntp++) {
            unsigned b0, b1, b2, b3;
            unsigned addr = sVu + ((kt*16 + (lane & 7) + ((lane >> 3) & 1)*8)*520 +
                warp*64 + ntp*16 + (lane >> 4)*8) * 2;
            LDSM4T(b0, b1, b2, b3, addr);
            MMA16816(acc[0][2*ntp],   a[0], b0, b1);
            MMA16816(acc[1][2*ntp],   a[1], b0, b1);
            MMA16816(acc[0][2*ntp+1], a[0], b2, b3);
            MMA16816(acc[1][2*ntp+1], a[1], b2, b3);
        }
    }

    #pragma unroll
    for (int mt = 0; mt < 2; mt++)
        #pragma unroll
        for (int nt = 0; nt < 8; nt++) {
            int row = mt*16 + gid;
            int col = pb0 + warp*64 + nt*8 + tg*2;
            size_t o0 = vbase + (size_t)row*NPIX + col;
            size_t o1 = o0 + (size_t)8*NPIX;
            *(__nv_bfloat162*)&g_ov[o0] = __floats2bfloat162_rn(acc[mt][nt][0], acc[mt][nt][1]);
            *(__nv_bfloat162*)&g_ov[o1] = __floats2bfloat162_rn(acc[mt][nt][2], acc[mt][nt][3]);
        }
}

// ---------------- K6: LN2 -> bf16 into g_xn ----------------
__global__ void __launch_bounds__(256) k_ln2(const float* __restrict__ w,
                                             const float* __restrict__ bia)
{
    const int blk = blockIdx.x;
    const int b  = blk >> 7;
    const int pt = (blk & 127) * 32;
    const int tid = threadIdx.x;
    const int p = tid & 31;
    const int part = tid >> 5;
    const size_t base = (size_t)b*C_*NPIX + pt + p;

    __shared__ float ss[8][32], qq[8][32], s_mu[32], s_is[32];
    float s = 0.f, sq = 0.f;
    #pragma unroll 8
    for (int j = 0; j < 32; j++) {
        float v = g_x1[base + (size_t)(part*32 + j)*NPIX];
        s += v; sq += v*v;
    }
    ss[part][p] = s; qq[part][p] = sq;
    __syncthreads();
    if (tid < 32) {
        float a = 0.f, c2 = 0.f;
        #pragma unroll
        for (int j = 0; j < 8; j++) { a += ss[j][tid]; c2 += qq[j][tid]; }
        float mu = a * (1.f/256.f);
        float var = c2 * (1.f/256.f) - mu*mu;
        s_mu[tid] = mu; s_is[tid] = rsqrtf(var + 1e-5f);
    }
    __syncthreads();
    float mu = s_mu[p], is = s_is[p];
    #pragma unroll 8
    for (int j = 0; j < 32; j++) {
        int c = part*32 + j;
        float v = g_x1[base + (size_t)c*NPIX];
        g_xn[base + (size_t)c*NPIX] = __float2bfloat16((v - mu)*is*w[c] + bia[c]);
    }
}

// ---------------- tensor-core GEMM (1x1 convs) ----------------
template<int MODE>
__global__ void __launch_bounds__(256) k_mma(const __nv_bfloat16* __restrict__ Wb,
                                             const __nv_bfloat16* __restrict__ Act,
                                             const float* __restrict__ res,
                                             float* __restrict__ outp)
{
    constexpr int O = (MODE == 1) ? 1360 : 256;
    constexpr int K = (MODE == 2) ? 680 : 256;
    constexpr int NC = (K + 31) / 32;
    constexpr int ASZ = 128*40;
    constexpr int BSZ = 32*136;

    const int b  = blockIdx.z;
    const int bn = blockIdx.x * 128;
    const int bm = blockIdx.y * 128;
    const int tid = threadIdx.x, lane = tid & 31, warp = tid >> 5;
    const int wm = warp >> 1, wn = warp & 1;
    const int gid = lane >> 2, tg = lane & 3;

    __shared__ __align__(16) __nv_bfloat16 sA[2][ASZ];
    __shared__ __align__(16) __nv_bfloat16 sB[2][BSZ];
    const unsigned sAu = (unsigned)__cvta_generic_to_shared(&sA[0][0]);
    const unsigned sBu = (unsigned)__cvta_generic_to_shared(&sB[0][0]);

    const int ar = tid >> 1, ac = (tid & 1) * 16;
    const int bk = tid >> 3, bn8 = (tid & 7) * 16;
    int arow = bm + ar; if (arow > O-1) arow = O-1;
    const __nv_bfloat16* Arow = Wb + (size_t)arow * K;
    const __nv_bfloat16* Bbase = Act + (size_t)b * K * NPIX + bn;

    float acc[2][8][4];
    #pragma unroll
    for (int i = 0; i < 2; i++)
        #pragma unroll
        for (int j = 0; j < 8; j++)
            #pragma unroll
            for (int q = 0; q < 4; q++) acc[i][j][q] = 0.f;

    auto load_chunk = [&](int c, int buf) {
        const int k0 = c * 32;
        #pragma unroll
        for (int j = 0; j < 2; j++) {
            int ko = ac + j*8;
            unsigned dst = sAu + (buf*ASZ + ar*40 + ko) * 2;
            if (k0 + ko < K) { CP16(dst, Arow + k0 + ko); }
            else *(float4*)(&sA[buf][ar*40 + ko]) = make_float4(0,0,0,0);
        }
        #pragma unroll
        for (int j = 0; j < 2; j++) {
            int no = bn8 + j*8;
            unsigned dst = sBu + (buf*BSZ + bk*136 + no) * 2;
            if (k0 + bk < K) { CP16(dst, Bbase + (size_t)(k0 + bk)*NPIX + no); }
            else *(float4*)(&sB[buf][bk*136 + no]) = make_float4(0,0,0,0);
        }
        asm volatile("cp.async.commit_group;" ::);
    };

    load_chunk(0, 0);

    for (int c = 0; c < NC; c++) {
        const int buf = c & 1;
        if (c + 1 < NC) {
            load_chunk(c + 1, (c + 1) & 1);
            asm volatile("cp.async.wait_group 1;" ::);
        } else {
            asm volatile("cp.async.wait_group 0;" ::);
        }
        __syncthreads();

        #pragma unroll
        for (int kt = 0; kt < 2; kt++) {
            unsigned a[2][4];
            #pragma unroll
            for (int mt = 0; mt < 2; mt++) {
                unsigned addr = sAu + (buf*ASZ +
                    (wm*32 + mt*16 + (lane & 15))*40 + kt*16 + (lane >> 4)*8) * 2;
                LDSM4(a[mt][0], a[mt][1], a[mt][2], a[mt][3], addr);
            }
            #pragma unroll
            for (int ntp = 0; ntp < 4; ntp++) {
                unsigned b0, b1, b2, b3;
                unsigned addr = sBu + (buf*BSZ +
                    (kt*16 + (lane & 7) + ((lane >> 3) & 1)*8)*136 +
                    wn*64 + ntp*16 + (lane >> 4)*8) * 2;
                LDSM4T(b0, b1, b2, b3, addr);
                MMA16816(acc[0][2*ntp],   a[0], b0, b1);
                MMA16816(acc[1][2*ntp],   a[1], b0, b1);
                MMA16816(acc[0][2*ntp+1], a[0], b2, b3);
                MMA16816(acc[1][2*ntp+1], a[1], b2, b3);
            }
        }
        __syncthreads();
    }

    #pragma unroll
    for (int mt = 0; mt < 2; mt++) {
        #pragma unroll
        for (int nt = 0; nt < 8; nt++) {
            int row = bm + wm*32 + mt*16 + gid;
            int col = bn + wn*64 + nt*8 + tg*2;
            float* a4 = acc[mt][nt];
            if (MODE == 0) {
                size_t o0 = ((size_t)b*256 + row)*NPIX + col;
                size_t o1 = o0 + (size_t)8*NPIX;
                float2 r0 = *(const float2*)&res[o0];
                float2 r1 = *(const float2*)&res[o1];
                *(float2*)&g_x1[o0] = make_float2(r0.x + a4[0], r0.y + a4[1]);
                *(float2*)&g_x1[o1] = make_float2(r1.x + a4[2], r1.y + a4[3]);
            } else if (MODE == 1) {
                if (row < 1360) {
                    size_t o0 = ((size_t)b*1360 + row)*NPIX + col;
                    *(__nv_bfloat162*)&g_t[o0] = __floats2bfloat162_rn(a4[0], a4[1]);
                }
                if (row + 8 < 1360) {
                    size_t o1 = ((size_t)b*1360 + row + 8)*NPIX + col;
                    *(__nv_bfloat162*)&g_t[o1] = __floats2bfloat162_rn(a4[2], a4[3]);
                }
            } else {
                size_t o0 = ((size_t)b*256 + row)*NPIX + col;
                size_t o1 = o0 + (size_t)8*NPIX;
                float2 r0 = *(const float2*)&g_x1[o0];
                float2 r1 = *(const float2*)&g_x1[o1];
                *(float2*)&outp[o0] = make_float2(r0.x + a4[0], r0.y + a4[1]);
                *(float2*)&outp[o1] = make_float2(r1.x + a4[2], r1.y + a4[3]);
            }
        }
    }
}

// ---------------- K8: depthwise + GELU gate ----------------
__global__ void __launch_bounds__(256) k_gate(const float* __restrict__ dw)
{
    const int blk = blockIdx.x;
    const int b = blk / HID_, i = blk % HID_;
    const int tid = threadIdx.x;
    __shared__ __nv_bfloat16 s1[PADW*PADW];
    __shared__ __nv_bfloat16 s2[PADW*PADW];

    const __nv_bfloat16 z = __float2bfloat16(0.f);
    for (int j = tid; j < PADW*PADW; j += 256) { s1[j] = z; s2[j] = z; }
    __syncthreads();
    const size_t base1 = ((size_t)b*2*HID_ + i) * NPIX;
    const size_t base2 = ((size_t)b*2*HID_ + HID_ + i) * NPIX;
    for (int j = tid; j < NPIX; j += 256) {
        int h = j >> 6, w = j & 63;
        s1[(h+1)*PADW + w + 1] = g_t[base1 + j];
        s2[(h+1)*PADW + w + 1] = g_t[base2 + j];
    }
    __syncthreads();

    float w1[9], w2[9];
    #pragma unroll
    for (int j = 0; j < 9; j++) {
        w1[j] = dw[i*9 + j];
        w2[j] = dw[(HID_ + i)*9 + j];
    }
    const size_t obase = ((size_t)b*HID_ + i) * NPIX;
    for (int j = tid; j < NPIX; j += 256) {
        int h = j >> 6, w = j & 63;
        int s0 = h*PADW + w;
        float a = 0.f, g = 0.f;
        #pragma unroll
        for (int dy = 0; dy < 3; dy++)
            #pragma unroll
            for (int dx = 0; dx < 3; dx++) {
                int t = dy*3 + dx;
                a = fmaf(__bfloat162float(s1[s0 + dy*PADW + dx]), w1[t], a);
                g = fmaf(__bfloat162float(s2[s0 + dy*PADW + dx]), w2[t], g);
            }
        float ge = 0.5f * a * (1.f + erff(a * 0.70710678118654752f));
        g_h[obase + j] = __float2bfloat16(ge * g);
    }
}

// ---------------- launch ----------------
extern "C" void kernel_launch(void* const* d_in, const int* in_sizes, int n_in,
                              void* d_out, int out_size)
{
    const float* x        = (const float*)d_in[0];
    const float* y        = (const float*)d_in[1];
    const float* ln1x_w   = (const float*)d_in[2];
    const float* ln1x_b   = (const float*)d_in[3];
    const float* ln1y_w   = (const float*)d_in[4];
    const float* ln1y_b   = (const float*)d_in[5];
    const float* ln2_w    = (const float*)d_in[6];
    const float* ln2_b    = (const float*)d_in[7];
    const float* temp     = (const float*)d_in[8];
    const float* qkv_dw   = (const float*)d_in[9];
    const float* proj_w   = (const float*)d_in[10];
    const float* ffn_in_w = (const float*)d_in[11];
    const float* ffn_dw   = (const float*)d_in[12];
    const float* ffn_out_w= (const float*)d_in[13];
    float* out = (float*)d_out;

    __nv_bfloat16 *wP, *wI, *wO;
    cudaGetSymbolAddress((void**)&wP, g_wP);
    cudaGetSymbolAddress((void**)&wI, g_wI);
    cudaGetSymbolAddress((void**)&wO, g_wO);
    __nv_bfloat16 *ov, *xn, *hh;
    cudaGetSymbolAddress((void**)&ov, g_ov);
    cudaGetSymbolAddress((void**)&xn, g_xn);
    cudaGetSymbolAddress((void**)&hh, g_h);

    k_cvtw<<<576, 256>>>(proj_w, ffn_in_w, ffn_out_w);
    k_ln1<<<B_*128, 256>>>(x, y, ln1x_w, ln1x_b, ln1y_w, ln1y_b);
    k_qkv<<<B_*C_, 256>>>(qkv_dw);
    k_qks<<<64, 256>>>(temp);
    k_av2<<<dim3(8, 64), 256>>>();
    k_mma<0><<<dim3(32, 2, B_), 256>>>(wP, ov, x, nullptr);
    k_ln2<<<B_*128, 256>>>(ln2_w, ln2_b);
    k_mma<1><<<dim3(32, 11, B_), 256>>>(wI, xn, nullptr, nullptr);
    k_gate<<<B_*HID_, 256>>>(ffn_dw);
    k_mma<2><<<dim3(32, 2, B_), 256>>>(wO, hh, nullptr, out);
}

// round 4
// speedup vs baseline: 3.1290x; 1.0743x over previous
#include <cuda_runtime.h>
#include <cuda_bf16.h>
#include <math.h>

#define B_ 8
#define C_ 256
#define NPIX 4096
#define HID_ 680
#define PADW 66

// ---------------- scratch ----------------
__device__ __nv_bfloat16 g_xn[B_*C_*NPIX];
__device__ __nv_bfloat16 g_yn[B_*C_*NPIX];
__device__ __nv_bfloat16 g_q [B_*C_*NPIX];
__device__ __nv_bfloat16 g_k [B_*C_*NPIX];
__device__ __nv_bfloat16 g_v [B_*C_*NPIX];
__device__ __nv_bfloat16 g_ov[B_*C_*NPIX];
__device__ float g_x1[B_*C_*NPIX];
__device__ float g_sumsq_q[B_*C_];
__device__ float g_sumsq_k[B_*C_];
__device__ float g_part[4*64*1024];          // split-K partials [seg][bh][c][d]
__device__ __nv_bfloat16 g_attnb[64*1024];   // [bh][c][d] bf16
__device__ __nv_bfloat16 g_t[B_*2*HID_*NPIX];
__device__ __nv_bfloat16 g_h[B_*HID_*NPIX];
// bf16 weights
__device__ __nv_bfloat16 g_wP[256*256];
__device__ __nv_bfloat16 g_wI[1360*256];
__device__ __nv_bfloat16 g_wO[256*680];

// ---------------- mma helpers ----------------
#define MMA16816(d, a, b0, b1) \
    asm volatile("mma.sync.aligned.m16n8k16.row.col.f32.bf16.bf16.f32 " \
        "{%0,%1,%2,%3},{%4,%5,%6,%7},{%8,%9},{%0,%1,%2,%3};" \
        : "+f"(d[0]),"+f"(d[1]),"+f"(d[2]),"+f"(d[3]) \
        : "r"(a[0]),"r"(a[1]),"r"(a[2]),"r"(a[3]),"r"(b0),"r"(b1))

#define LDSM4(r0,r1,r2,r3,addr) \
    asm volatile("ldmatrix.sync.aligned.m8n8.x4.shared.b16 {%0,%1,%2,%3},[%4];" \
        : "=r"(r0),"=r"(r1),"=r"(r2),"=r"(r3) : "r"(addr))

#define LDSM4T(r0,r1,r2,r3,addr) \
    asm volatile("ldmatrix.sync.aligned.m8n8.x4.trans.shared.b16 {%0,%1,%2,%3},[%4];" \
        : "=r"(r0),"=r"(r1),"=r"(r2),"=r"(r3) : "r"(addr))

#define CP16(dst, src) \
    asm volatile("cp.async.cg.shared.global [%0], [%1], 16;" :: "r"(dst), "l"(src))

// ---------------- weight convert ----------------
__global__ void k_cvtw(const float* __restrict__ p, const float* __restrict__ wi,
                       const float* __restrict__ wo)
{
    const int NP = 256*256, NI = 1360*256, NO = 256*680;
    for (int i = blockIdx.x*256 + threadIdx.x; i < NP+NI+NO; i += gridDim.x*256) {
        if (i < NP) g_wP[i] = __float2bfloat16(p[i]);
        else if (i < NP+NI) g_wI[i-NP] = __float2bfloat16(wi[i-NP]);
        else g_wO[i-NP-NI] = __float2bfloat16(wo[i-NP-NI]);
    }
}

// ---------------- K1: LayerNorm x,y ----------------
__global__ void __launch_bounds__(256) k_ln1(
    const float* __restrict__ x, const float* __restrict__ y,
    const float* __restrict__ xw, const float* __restrict__ xb,
    const float* __restrict__ yw, const float* __restrict__ yb)
{
    const int blk = blockIdx.x;
    const int b   = blk >> 7;
    const int pt  = (blk & 127) * 32;
    const int tid = threadIdx.x;
    const int p    = tid & 31;
    const int part = tid >> 5;
    const size_t base = (size_t)b*C_*NPIX + pt + p;

    __shared__ float s_s[8][32], s_q[8][32], s_mu[32], s_is[32];

    {
        float s = 0.f, sq = 0.f;
        #pragma unroll 8
        for (int j = 0; j < 32; j++) {
            float v = x[base + (size_t)(part*32 + j)*NPIX];
            s += v; sq += v*v;
        }
        s_s[part][p] = s; s_q[part][p] = sq;
        __syncthreads();
        if (tid < 32) {
            float a = 0.f, c2 = 0.f;
            #pragma unroll
            for (int j = 0; j < 8; j++) { a += s_s[j][tid]; c2 += s_q[j][tid]; }
            float mu = a * (1.f/256.f);
            float var = c2 * (1.f/256.f) - mu*mu;
            s_mu[tid] = mu; s_is[tid] = rsqrtf(var + 1e-5f);
        }
        __syncthreads();
        float mu = s_mu[p], is = s_is[p];
        #pragma unroll 8
        for (int j = 0; j < 32; j++) {
            int c = part*32 + j;
            float v = x[base + (size_t)c*NPIX];
            g_xn[base + (size_t)c*NPIX] = __float2bfloat16((v - mu)*is*xw[c] + xb[c]);
        }
    }
    __syncthreads();
    {
        float s = 0.f, sq = 0.f;
        #pragma unroll 8
        for (int j = 0; j < 32; j++) {
            float v = y[base + (size_t)(part*32 + j)*NPIX];
            s += v; sq += v*v;
        }
        s_s[part][p] = s; s_q[part][p] = sq;
        __syncthreads();
        if (tid < 32) {
            float a = 0.f, c2 = 0.f;
            #pragma unroll
            for (int j = 0; j < 8; j++) { a += s_s[j][tid]; c2 += s_q[j][tid]; }
            float mu = a * (1.f/256.f);
            float var = c2 * (1.f/256.f) - mu*mu;
            s_mu[tid] = mu; s_is[tid] = rsqrtf(var + 1e-5f);
        }
        __syncthreads();
        float mu = s_mu[p], is = s_is[p];
        #pragma unroll 8
        for (int j = 0; j < 32; j++) {
            int c = part*32 + j;
            float v = y[base + (size_t)c*NPIX];
            g_yn[base + (size_t)c*NPIX] = __float2bfloat16((v - mu)*is*yw[c] + yb[c]);
        }
    }
}

// ---------------- K2: depthwise QKV + sumsq ----------------
__global__ void __launch_bounds__(256) k_qkv(const float* __restrict__ dw)
{
    const int blk = blockIdx.x;
    const int c   = blk & 255;
    const int tid = threadIdx.x;
    __shared__ __nv_bfloat16 sx[PADW*PADW];
    __shared__ __nv_bfloat16 sy[PADW*PADW];

    const __nv_bfloat16 z = __float2bfloat16(0.f);
    for (int i = tid; i < PADW*PADW; i += 256) { sx[i] = z; sy[i] = z; }
    __syncthreads();
    const size_t pbase = (size_t)blk * NPIX;
    for (int i = tid; i < NPIX; i += 256) {
        int h = i >> 6, w = i & 63;
        sx[(h+1)*PADW + w + 1] = g_xn[pbase + i];
        sy[(h+1)*PADW + w + 1] = g_yn[pbase + i];
    }
    __syncthreads();

    float wq[9], wk[9], wv[9];
    #pragma unroll
    for (int j = 0; j < 9; j++) {
        wq[j] = dw[c*9 + j];
        wk[j] = dw[(256 + c)*9 + j];
        wv[j] = dw[(512 + c)*9 + j];
    }

    float sqq = 0.f, sqk = 0.f;
    for (int i = tid; i < NPIX; i += 256) {
        int h = i >> 6, w = i & 63;
        int s0 = h*PADW + w;
        float q = 0.f, k = 0.f, v = 0.f;
        #pragma unroll
        for (int dy = 0; dy < 3; dy++)
            #pragma unroll
            for (int dx = 0; dx < 3; dx++) {
                float xv = __bfloat162float(sx[s0 + dy*PADW + dx]);
                float yv = __bfloat162float(sy[s0 + dy*PADW + dx]);
                int t = dy*3 + dx;
                q = fmaf(xv, wq[t], q);
                k = fmaf(yv, wk[t], k);
                v = fmaf(yv, wv[t], v);
            }
        g_q[pbase + i] = __float2bfloat16(q);
        g_k[pbase + i] = __float2bfloat16(k);
        g_v[pbase + i] = __float2bfloat16(v);
        sqq += q*q; sqk += k*k;
    }
    #pragma unroll
    for (int off = 16; off; off >>= 1) {
        sqq += __shfl_down_sync(0xffffffffu, sqq, off);
        sqk += __shfl_down_sync(0xffffffffu, sqk, off);
    }
    __shared__ float rq[8], rk[8];
    if ((tid & 31) == 0) { rq[tid >> 5] = sqq; rk[tid >> 5] = sqk; }
    __syncthreads();
    if (tid == 0) {
        float a = 0.f, bqv = 0.f;
        #pragma unroll
        for (int j = 0; j < 8; j++) { a += rq[j]; bqv += rk[j]; }
        g_sumsq_q[blk] = a;
        g_sumsq_k[blk] = bqv;
    }
}

// ---------------- K3: QK^T partials (split-K, mma) ----------------
__global__ void __launch_bounds__(256) k_qks()
{
    const int seg = blockIdx.x;   // 0..3  (1024 pixels each)
    const int bh  = blockIdx.y;   // 0..63
    const int b = bh >> 3, h = bh & 7;
    const int tid = threadIdx.x, lane = tid & 31, warp = tid >> 5;
    const int gid = lane >> 2, tg = lane & 3;

    __shared__ __align__(16) char smraw[2*2*32*136*2];
    __nv_bfloat16* sQ = (__nv_bfloat16*)smraw;          // [2][32*136]
    __nv_bfloat16* sK = sQ + 2*32*136;
    float* stage = (float*)smraw;                       // reused after mma loop
    const unsigned sQu = (unsigned)__cvta_generic_to_shared(sQ);
    const unsigned sKu = (unsigned)__cvta_generic_to_shared(sK);

    const size_t base = ((size_t)b*C_ + h*32) * NPIX;
    const int r  = tid >> 3;
    const int cg = (tid & 7) * 16;

    auto prefetch = [&](int c, int buf) {
        const int n0 = seg*1024 + c * 128;
        const __nv_bfloat16* qp = g_q + base + (size_t)r*NPIX + n0 + cg;
        const __nv_bfloat16* kp = g_k + base + (size_t)r*NPIX + n0 + cg;
        unsigned dq = sQu + (buf*32*136 + r*136 + cg) * 2;
        unsigned dk = sKu + (buf*32*136 + r*136 + cg) * 2;
        CP16(dq,      qp);
        CP16(dq + 16, qp + 8);
        CP16(dk,      kp);
        CP16(dk + 16, kp + 8);
        asm volatile("cp.async.commit_group;" ::);
    };

    float acc[2][4][4];
    #pragma unroll
    for (int i = 0; i < 2; i++)
        #pragma unroll
        for (int j = 0; j < 4; j++)
            #pragma unroll
            for (int q = 0; q < 4; q++) acc[i][j][q] = 0.f;

    prefetch(0, 0);

    for (int c = 0; c < 8; c++) {
        const int buf = c & 1;
        if (c + 1 < 8) {
            prefetch(c + 1, buf ^ 1);
            asm volatile("cp.async.wait_group 1;" ::);
        } else {
            asm volatile("cp.async.wait_group 0;" ::);
        }
        __syncthreads();

        const int col = warp*16 + (lane >> 4)*8;
        unsigned a[2][4];
        #pragma unroll
        for (int mt = 0; mt < 2; mt++) {
            unsigned addr = sQu + (buf*32*136 + (mt*16 + (lane & 15))*136 + col) * 2;
            LDSM4(a[mt][0], a[mt][1], a[mt][2], a[mt][3], addr);
        }
        #pragma unroll
        for (int nt = 0; nt < 2; nt++) {
            unsigned r0, r1, r2, r3;
            unsigned addr = sKu + (buf*32*136 + (nt*16 + (lane & 15))*136 + col) * 2;
            LDSM4(r0, r1, r2, r3, addr);
            MMA16816(acc[0][nt*2],   a[0], r0, r2);
            MMA16816(acc[1][nt*2],   a[1], r0, r2);
            MMA16816(acc[0][nt*2+1], a[0], r1, r3);
            MMA16816(acc[1][nt*2+1], a[1], r1, r3);
        }
        __syncthreads();
    }

    // cross-warp reduce in smem: stage[w][c][d], stride 33
    #pragma unroll
    for (int mt = 0; mt < 2; mt++)
        #pragma unroll
        for (int j = 0; j < 4; j++) {
            int c0 = mt*16 + gid, d0 = j*8 + tg*2;
            stage[warp*1056 + c0*33 + d0]       = acc[mt][j][0];
            stage[warp*1056 + c0*33 + d0 + 1]   = acc[mt][j][1];
            stage[warp*1056 + (c0+8)*33 + d0]   = acc[mt][j][2];
            stage[warp*1056 + (c0+8)*33 + d0+1] = acc[mt][j][3];
        }
    __syncthreads();

    const int cc = tid >> 3;
    const int dg = (tid & 7) * 4;
    float4 v = make_float4(0.f, 0.f, 0.f, 0.f);
    #pragma unroll
    for (int w = 0; w < 8; w++) {
        const float* sp = &stage[w*1056 + cc*33 + dg];
        v.x += sp[0]; v.y += sp[1]; v.z += sp[2]; v.w += sp[3];
    }
    *(float4*)&g_part[(((size_t)seg*64 + bh)*32 + cc)*32 + dg] = v;
}

// ---------------- K4: reduce partials + scale + softmax ----------------
__global__ void __launch_bounds__(256) k_soft(const float* __restrict__ temp)
{
    const int bh = blockIdx.x;
    const int b = bh >> 3, h = bh & 7;
    const int tid = threadIdx.x;
    const int cc = tid >> 3;
    const int dg = (tid & 7) * 4;
    const float t = temp[h];

    float v[4] = {0.f, 0.f, 0.f, 0.f};
    #pragma unroll
    for (int sg = 0; sg < 4; sg++) {
        float4 l = *(const float4*)&g_part[(((size_t)sg*64 + bh)*32 + cc)*32 + dg];
        v[0] += l.x; v[1] += l.y; v[2] += l.z; v[3] += l.w;
    }
    float nq = sqrtf(g_sumsq_q[b*C_ + h*32 + cc]);
    float rq = 1.f / fmaxf(nq, 1e-12f);
    float mx = -1e30f;
    #pragma unroll
    for (int j = 0; j < 4; j++) {
        float nk = sqrtf(g_sumsq_k[b*C_ + h*32 + dg + j]);
        v[j] *= rq * (1.f / fmaxf(nk, 1e-12f)) * t;
        mx = fmaxf(mx, v[j]);
    }
    #pragma unroll
    for (int m = 1; m < 8; m <<= 1) mx = fmaxf(mx, __shfl_xor_sync(0xffffffffu, mx, m));
    float sum = 0.f;
    #pragma unroll
    for (int j = 0; j < 4; j++) { v[j] = expf(v[j] - mx); sum += v[j]; }
    #pragma unroll
    for (int m = 1; m < 8; m <<= 1) sum += __shfl_xor_sync(0xffffffffu, sum, m);
    float inv = 1.f / sum;
    __nv_bfloat162* op = reinterpret_cast<__nv_bfloat162*>(&g_attnb[(size_t)bh*1024 + cc*32 + dg]);
    op[0] = __floats2bfloat162_rn(v[0]*inv, v[1]*inv);
    op[1] = __floats2bfloat162_rn(v[2]*inv, v[3]*inv);
}

// ---------------- K5: out = attn @ v (mma) ----------------
__global__ void __launch_bounds__(256) k_av2()
{
    const int seg = blockIdx.x;
    const int bh  = blockIdx.y;
    const int b = bh >> 3, h = bh & 7;
    const int tid = threadIdx.x, lane = tid & 31, warp = tid >> 5;
    const int gid = lane >> 2, tg = lane & 3;

    __shared__ __align__(16) __nv_bfloat16 sA[32*40];
    __shared__ __align__(16) __nv_bfloat16 sV[32*520];
    const unsigned sAu = (unsigned)__cvta_generic_to_shared(&sA[0]);
    const unsigned sVu = (unsigned)__cvta_generic_to_shared(&sV[0]);

    {
        int c0 = tid >> 3, d0 = (tid & 7) * 4;
        const __nv_bfloat162* ap = reinterpret_cast<const __nv_bfloat162*>(
            &g_attnb[(size_t)bh*1024 + c0*32 + d0]);
        __nv_bfloat162* sp = reinterpret_cast<__nv_bfloat162*>(&sA[c0*40 + d0]);
        sp[0] = ap[0]; sp[1] = ap[1];
    }
    const size_t vbase = ((size_t)b*C_ + h*32) * NPIX;
    const int pb0 = seg * 512;
    {
        int r = tid >> 3, cg = (tid & 7) * 64;
        #pragma unroll
        for (int j = 0; j < 8; j++)
            *(float4*)&sV[r*520 + cg + j*8] =
                *(const float4*)&g_v[vbase + (size_t)r*NPIX + pb0 + cg + j*8];
    }
    __syncthreads();

    float acc[2][8][4];
    #pragma unroll
    for (int i = 0; i < 2; i++)
        #pragma unroll
        for (int j = 0; j < 8; j++)
            #pragma unroll
            for (int q = 0; q < 4; q++) acc[i][j][q] = 0.f;

    #pragma unroll
    for (int kt = 0; kt < 2; kt++) {
        unsigned a[2][4];
        #pragma unroll
        for (int mt = 0; mt < 2; mt++) {
            unsigned addr = sAu + ((mt*16 + (lane & 15))*40 + kt*16 + (lane >> 4)*8) * 2;
            LDSM4(a[mt][0], a[mt][1], a[mt][2], a[mt][3], addr);
        }
        #pragma unroll
        for (int ntp = 0; ntp < 4; ntp++) {
            unsigned b0, b1, b2, b3;
            unsigned addr = sVu + ((kt*16 + (lane & 7) + ((lane >> 3) & 1)*8)*520 +
                warp*64 + ntp*16 + (lane >> 4)*8) * 2;
            LDSM4T(b0, b1, b2, b3, addr);
            MMA16816(acc[0][2*ntp],   a[0], b0, b1);
            MMA16816(acc[1][2*ntp],   a[1], b0, b1);
            MMA16816(acc[0][2*ntp+1], a[0], b2, b3);
            MMA16816(acc[1][2*ntp+1], a[1], b2, b3);
        }
    }

    #pragma unroll
    for (int mt = 0; mt < 2; mt++)
        #pragma unroll
        for (int nt = 0; nt < 8; nt++) {
            int row = mt*16 + gid;
            int col = pb0 + warp*64 + nt*8 + tg*2;
            size_t o0 = vbase + (size_t)row*NPIX + col;
            size_t o1 = o0 + (size_t)8*NPIX;
            *(__nv_bfloat162*)&g_ov[o0] = __floats2bfloat162_rn(acc[mt][nt][0], acc[mt][nt][1]);
            *(__nv_bfloat162*)&g_ov[o1] = __floats2bfloat162_rn(acc[mt][nt][2], acc[mt][nt][3]);
        }
}

// ---------------- K6: LN2 -> bf16 into g_xn ----------------
__global__ void __launch_bounds__(256) k_ln2(const float* __restrict__ w,
                                             const float* __restrict__ bia)
{
    const int blk = blockIdx.x;
    const int b  = blk >> 7;
    const int pt = (blk & 127) * 32;
    const int tid = threadIdx.x;
    const int p = tid & 31;
    const int part = tid >> 5;
    const size_t base = (size_t)b*C_*NPIX + pt + p;

    __shared__ float ss[8][32], qq[8][32], s_mu[32], s_is[32];
    float s = 0.f, sq = 0.f;
    #pragma unroll 8
    for (int j = 0; j < 32; j++) {
        float v = g_x1[base + (size_t)(part*32 + j)*NPIX];
        s += v; sq += v*v;
    }
    ss[part][p] = s; qq[part][p] = sq;
    __syncthreads();
    if (tid < 32) {
        float a = 0.f, c2 = 0.f;
        #pragma unroll
        for (int j = 0; j < 8; j++) { a += ss[j][tid]; c2 += qq[j][tid]; }
        float mu = a * (1.f/256.f);
        float var = c2 * (1.f/256.f) - mu*mu;
        s_mu[tid] = mu; s_is[tid] = rsqrtf(var + 1e-5f);
    }
    __syncthreads();
    float mu = s_mu[p], is = s_is[p];
    #pragma unroll 8
    for (int j = 0; j < 32; j++) {
        int c = part*32 + j;
        float v = g_x1[base + (size_t)c*NPIX];
        g_xn[base + (size_t)c*NPIX] = __float2bfloat16((v - mu)*is*w[c] + bia[c]);
    }
}

// ---------------- tensor-core GEMM (1x1 convs), 4-stage pipeline ----------------
template<int MODE>
__global__ void __launch_bounds__(256) k_mma(const __nv_bfloat16* __restrict__ Wb,
                                             const __nv_bfloat16* __restrict__ Act,
                                             const float* __restrict__ res,
                                             float* __restrict__ outp)
{
    constexpr int O = (MODE == 1) ? 1360 : 256;
    constexpr int K = (MODE == 2) ? 680 : 256;
    constexpr int NC = (K + 31) / 32;
    constexpr int ASZ = 128*40;
    constexpr int BSZ = 32*136;

    const int b  = blockIdx.z;
    const int bn = blockIdx.x * 128;
    const int bm = blockIdx.y * 128;
    const int tid = threadIdx.x, lane = tid & 31, warp = tid >> 5;
    const int wm = warp >> 1, wn = warp & 1;
    const int gid = lane >> 2, tg = lane & 3;

    __shared__ __align__(16) __nv_bfloat16 sA[4][ASZ];
    __shared__ __align__(16) __nv_bfloat16 sB[4][BSZ];
    const unsigned sAu = (unsigned)__cvta_generic_to_shared(&sA[0][0]);
    const unsigned sBu = (unsigned)__cvta_generic_to_shared(&sB[0][0]);

    const int ar = tid >> 1, ac = (tid & 1) * 16;
    const int bk = tid >> 3, bn8 = (tid & 7) * 16;
    int arow = bm + ar; if (arow > O-1) arow = O-1;
    const __nv_bfloat16* Arow = Wb + (size_t)arow * K;
    const __nv_bfloat16* Bbase = Act + (size_t)b * K * NPIX + bn;

    float acc[2][8][4];
    #pragma unroll
    for (int i = 0; i < 2; i++)
        #pragma unroll
        for (int j = 0; j < 8; j++)
            #pragma unroll
            for (int q = 0; q < 4; q++) acc[i][j][q] = 0.f;

    auto load_chunk = [&](int c, int buf) {
        const int k0 = c * 32;
        #pragma unroll
        for (int j = 0; j < 2; j++) {
            int ko = ac + j*8;
            unsigned dst = sAu + (buf*ASZ + ar*40 + ko) * 2;
            if (k0 + ko < K) { CP16(dst, Arow + k0 + ko); }
            else *(float4*)(&sA[buf][ar*40 + ko]) = make_float4(0,0,0,0);
        }
        #pragma unroll
        for (int j = 0; j < 2; j++) {
            int no = bn8 + j*8;
            unsigned dst = sBu + (buf*BSZ + bk*136 + no) * 2;
            if (k0 + bk < K) { CP16(dst, Bbase + (size_t)(k0 + bk)*NPIX + no); }
            else *(float4*)(&sB[buf][bk*136 + no]) = make_float4(0,0,0,0);
        }
        asm volatile("cp.async.commit_group;" ::);
    };

    load_chunk(0, 0);
    load_chunk(1, 1);
    load_chunk(2, 2);

    for (int c = 0; c < NC; c++) {
        const int buf = c & 3;
        const int rem = NC - 1 - c;
        if (rem >= 2)      { asm volatile("cp.async.wait_group 2;" ::); }
        else if (rem == 1) { asm volatile("cp.async.wait_group 1;" ::); }
        else               { asm volatile("cp.async.wait_group 0;" ::); }
        __syncthreads();
        if (c + 3 < NC) load_chunk(c + 3, (c + 3) & 3);

        #pragma unroll
        for (int kt = 0; kt < 2; kt++) {
            unsigned a[2][4];
            #pragma unroll
            for (int mt = 0; mt < 2; mt++) {
                unsigned addr = sAu + (buf*ASZ +
                    (wm*32 + mt*16 + (lane & 15))*40 + kt*16 + (lane >> 4)*8) * 2;
                LDSM4(a[mt][0], a[mt][1], a[mt][2], a[mt][3], addr);
            }
            #pragma unroll
            for (int ntp = 0; ntp < 4; ntp++) {
                unsigned b0, b1, b2, b3;
                unsigned addr = sBu + (buf*BSZ +
                    (kt*16 + (lane & 7) + ((lane >> 3) & 1)*8)*136 +
                    wn*64 + ntp*16 + (lane >> 4)*8) * 2;
                LDSM4T(b0, b1, b2, b3, addr);
                MMA16816(acc[0][2*ntp],   a[0], b0, b1);
                MMA16816(acc[1][2*ntp],   a[1], b0, b1);
                MMA16816(acc[0][2*ntp+1], a[0], b2, b3);
                MMA16816(acc[1][2*ntp+1], a[1], b2, b3);
            }
        }
    }

    #pragma unroll
    for (int mt = 0; mt < 2; mt++) {
        #pragma unroll
        for (int nt = 0; nt < 8; nt++) {
            int row = bm + wm*32 + mt*16 + gid;
            int col = bn + wn*64 + nt*8 + tg*2;
            float* a4 = acc[mt][nt];
            if (MODE == 0) {
                size_t o0 = ((size_t)b*256 + row)*NPIX + col;
                size_t o1 = o0 + (size_t)8*NPIX;
                float2 r0 = *(const float2*)&res[o0];
                float2 r1 = *(const float2*)&res[o1];
                *(float2*)&g_x1[o0] = make_float2(r0.x + a4[0], r0.y + a4[1]);
                *(float2*)&g_x1[o1] = make_float2(r1.x + a4[2], r1.y + a4[3]);
            } else if (MODE == 1) {
                if (row < 1360) {
                    size_t o0 = ((size_t)b*1360 + row)*NPIX + col;
                    *(__nv_bfloat162*)&g_t[o0] = __floats2bfloat162_rn(a4[0], a4[1]);
                }
                if (row + 8 < 1360) {
                    size_t o1 = ((size_t)b*1360 + row + 8)*NPIX + col;
                    *(__nv_bfloat162*)&g_t[o1] = __floats2bfloat162_rn(a4[2], a4[3]);
                }
            } else {
                size_t o0 = ((size_t)b*256 + row)*NPIX + col;
                size_t o1 = o0 + (size_t)8*NPIX;
                float2 r0 = *(const float2*)&g_x1[o0];
                float2 r1 = *(const float2*)&g_x1[o1];
                *(float2*)&outp[o0] = make_float2(r0.x + a4[0], r0.y + a4[1]);
                *(float2*)&outp[o1] = make_float2(r1.x + a4[2], r1.y + a4[3]);
            }
        }
    }
}

// ---------------- K8: depthwise + GELU gate ----------------
__global__ void __launch_bounds__(256) k_gate(const float* __restrict__ dw)
{
    const int blk = blockIdx.x;
    const int b = blk / HID_, i = blk % HID_;
    const int tid = threadIdx.x;
    __shared__ __nv_bfloat16 s1[PADW*PADW];
    __shared__ __nv_bfloat16 s2[PADW*PADW];

    const __nv_bfloat16 z = __float2bfloat16(0.f);
    for (int j = tid; j < PADW*PADW; j += 256) { s1[j] = z; s2[j] = z; }
    __syncthreads();
    const size_t base1 = ((size_t)b*2*HID_ + i) * NPIX;
    const size_t base2 = ((size_t)b*2*HID_ + HID_ + i) * NPIX;
    for (int j = tid; j < NPIX; j += 256) {
        int h = j >> 6, w = j & 63;
        s1[(h+1)*PADW + w + 1] = g_t[base1 + j];
        s2[(h+1)*PADW + w + 1] = g_t[base2 + j];
    }
    __syncthreads();

    float w1[9], w2[9];
    #pragma unroll
    for (int j = 0; j < 9; j++) {
        w1[j] = dw[i*9 + j];
        w2[j] = dw[(HID_ + i)*9 + j];
    }
    const size_t obase = ((size_t)b*HID_ + i) * NPIX;
    for (int j = tid; j < NPIX; j += 256) {
        int h = j >> 6, w = j & 63;
        int s0 = h*PADW + w;
        float a = 0.f, g = 0.f;
        #pragma unroll
        for (int dy = 0; dy < 3; dy++)
            #pragma unroll
            for (int dx = 0; dx < 3; dx++) {
                int t = dy*3 + dx;
                a = fmaf(__bfloat162float(s1[s0 + dy*PADW + dx]), w1[t], a);
                g = fmaf(__bfloat162float(s2[s0 + dy*PADW + dx]), w2[t], g);
            }
        float ge = 0.5f * a * (1.f + erff(a * 0.70710678118654752f));
        g_h[obase + j] = __float2bfloat16(ge * g);
    }
}

// ---------------- launch ----------------
extern "C" void kernel_launch(void* const* d_in, const int* in_sizes, int n_in,
                              void* d_out, int out_size)
{
    const float* x        = (const float*)d_in[0];
    const float* y        = (const float*)d_in[1];
    const float* ln1x_w   = (const float*)d_in[2];
    const float* ln1x_b   = (const float*)d_in[3];
    const float* ln1y_w   = (const float*)d_in[4];
    const float* ln1y_b   = (const float*)d_in[5];
    const float* ln2_w    = (const float*)d_in[6];
    const float* ln2_b    = (const float*)d_in[7];
    const float* temp     = (const float*)d_in[8];
    const float* qkv_dw   = (const float*)d_in[9];
    const float* proj_w   = (const float*)d_in[10];
    const float* ffn_in_w = (const float*)d_in[11];
    const float* ffn_dw   = (const float*)d_in[12];
    const float* ffn_out_w= (const float*)d_in[13];
    float* out = (float*)d_out;

    __nv_bfloat16 *wP, *wI, *wO;
    cudaGetSymbolAddress((void**)&wP, g_wP);
    cudaGetSymbolAddress((void**)&wI, g_wI);
    cudaGetSymbolAddress((void**)&wO, g_wO);
    __nv_bfloat16 *ov, *xn, *hh;
    cudaGetSymbolAddress((void**)&ov, g_ov);
    cudaGetSymbolAddress((void**)&xn, g_xn);
    cudaGetSymbolAddress((void**)&hh, g_h);

    k_cvtw<<<576, 256>>>(proj_w, ffn_in_w, ffn_out_w);
    k_ln1<<<B_*128, 256>>>(x, y, ln1x_w, ln1x_b, ln1y_w, ln1y_b);
    k_qkv<<<B_*C_, 256>>>(qkv_dw);
    k_qks<<<dim3(4, 64), 256>>>();
    k_soft<<<64, 256>>>(temp);
    k_av2<<<dim3(8, 64), 256>>>();
    k_mma<0><<<dim3(32, 2, B_), 256>>>(wP, ov, x, nullptr);
    k_ln2<<<B_*128, 256>>>(ln2_w, ln2_b);
    k_mma<1><<<dim3(32, 11, B_), 256>>>(wI, xn, nullptr, nullptr);
    k_gate<<<B_*HID_, 256>>>(ffn_dw);
    k_mma<2><<<dim3(32, 2, B_), 256>>>(wO, hh, nullptr, out);
}

// round 5
// speedup vs baseline: 3.7037x; 1.1837x over previous
#include <cuda_runtime.h>
#include <cuda_bf16.h>
#include <math.h>

#define B_ 8
#define C_ 256
#define NPIX 4096
#define HID_ 680
#define SROW 80   // smem plane row stride (bf16), data starts at col 8

// ---------------- scratch ----------------
__device__ __nv_bfloat16 g_xn[B_*C_*NPIX];
__device__ __nv_bfloat16 g_yn[B_*C_*NPIX];
__device__ __nv_bfloat16 g_q [B_*C_*NPIX];
__device__ __nv_bfloat16 g_k [B_*C_*NPIX];
__device__ __nv_bfloat16 g_v [B_*C_*NPIX];
__device__ __nv_bfloat16 g_ov[B_*C_*NPIX];
__device__ float g_x1[B_*C_*NPIX];
__device__ float g_sumsq_q[B_*C_];
__device__ float g_sumsq_k[B_*C_];
__device__ float g_part[8*64*1024];          // split-K partials [seg][bh][c][d]
__device__ __nv_bfloat16 g_attnb[64*1024];
__device__ __nv_bfloat16 g_t[B_*2*HID_*NPIX];
__device__ __nv_bfloat16 g_h[B_*HID_*NPIX];
__device__ __nv_bfloat16 g_wP[256*256];
__device__ __nv_bfloat16 g_wI[1360*256];
__device__ __nv_bfloat16 g_wO[256*680];

// ---------------- mma helpers ----------------
#define MMA16816(d, a, b0, b1) \
    asm volatile("mma.sync.aligned.m16n8k16.row.col.f32.bf16.bf16.f32 " \
        "{%0,%1,%2,%3},{%4,%5,%6,%7},{%8,%9},{%0,%1,%2,%3};" \
        : "+f"(d[0]),"+f"(d[1]),"+f"(d[2]),"+f"(d[3]) \
        : "r"(a[0]),"r"(a[1]),"r"(a[2]),"r"(a[3]),"r"(b0),"r"(b1))

#define LDSM4(r0,r1,r2,r3,addr) \
    asm volatile("ldmatrix.sync.aligned.m8n8.x4.shared.b16 {%0,%1,%2,%3},[%4];" \
        : "=r"(r0),"=r"(r1),"=r"(r2),"=r"(r3) : "r"(addr))

#define LDSM4T(r0,r1,r2,r3,addr) \
    asm volatile("ldmatrix.sync.aligned.m8n8.x4.trans.shared.b16 {%0,%1,%2,%3},[%4];" \
        : "=r"(r0),"=r"(r1),"=r"(r2),"=r"(r3) : "r"(addr))

#define CP16(dst, src) \
    asm volatile("cp.async.cg.shared.global [%0], [%1], 16;" :: "r"(dst), "l"(src))

__device__ __forceinline__ unsigned packbf2(float a, float b) {
    __nv_bfloat162 h = __floats2bfloat162_rn(a, b);
    return *reinterpret_cast<unsigned*>(&h);
}

// ---------------- weight convert ----------------
__global__ void k_cvtw(const float* __restrict__ p, const float* __restrict__ wi,
                       const float* __restrict__ wo)
{
    const int NP = 256*256, NI = 1360*256, NO = 256*680;
    for (int i = blockIdx.x*256 + threadIdx.x; i < NP+NI+NO; i += gridDim.x*256) {
        if (i < NP) g_wP[i] = __float2bfloat16(p[i]);
        else if (i < NP+NI) g_wI[i-NP] = __float2bfloat16(wi[i-NP]);
        else g_wO[i-NP-NI] = __float2bfloat16(wo[i-NP-NI]);
    }
}

// ---------------- K1: LayerNorm x,y (register-cached single read) ----------------
__global__ void __launch_bounds__(256) k_ln1(
    const float* __restrict__ x, const float* __restrict__ y,
    const float* __restrict__ xw, const float* __restrict__ xb,
    const float* __restrict__ yw, const float* __restrict__ yb)
{
    const int blk = blockIdx.x;
    const int b   = blk >> 7;
    const int pt  = (blk & 127) * 32;
    const int tid = threadIdx.x;
    const int p    = tid & 31;
    const int part = tid >> 5;
    const size_t base = (size_t)b*C_*NPIX + pt + p;

    __shared__ float s_s[8][32], s_q[8][32], s_mu[32], s_is[32];
    float v[32];

    // ----- x -----
    {
        float s = 0.f, sq = 0.f;
        #pragma unroll 8
        for (int j = 0; j < 32; j++) {
            v[j] = x[base + (size_t)(part*32 + j)*NPIX];
            s += v[j]; sq += v[j]*v[j];
        }
        s_s[part][p] = s; s_q[part][p] = sq;
        __syncthreads();
        if (tid < 32) {
            float a = 0.f, c2 = 0.f;
            #pragma unroll
            for (int j = 0; j < 8; j++) { a += s_s[j][tid]; c2 += s_q[j][tid]; }
            float mu = a * (1.f/256.f);
            float var = c2 * (1.f/256.f) - mu*mu;
            s_mu[tid] = mu; s_is[tid] = rsqrtf(var + 1e-5f);
        }
        __syncthreads();
        float mu = s_mu[p], is = s_is[p];
        #pragma unroll 8
        for (int j = 0; j < 32; j++) {
            int c = part*32 + j;
            g_xn[base + (size_t)c*NPIX] = __float2bfloat16((v[j] - mu)*is*xw[c] + xb[c]);
        }
    }
    __syncthreads();
    // ----- y -----
    {
        float s = 0.f, sq = 0.f;
        #pragma unroll 8
        for (int j = 0; j < 32; j++) {
            v[j] = y[base + (size_t)(part*32 + j)*NPIX];
            s += v[j]; sq += v[j]*v[j];
        }
        s_s[part][p] = s; s_q[part][p] = sq;
        __syncthreads();
        if (tid < 32) {
            float a = 0.f, c2 = 0.f;
            #pragma unroll
            for (int j = 0; j < 8; j++) { a += s_s[j][tid]; c2 += s_q[j][tid]; }
            float mu = a * (1.f/256.f);
            float var = c2 * (1.f/256.f) - mu*mu;
            s_mu[tid] = mu; s_is[tid] = rsqrtf(var + 1e-5f);
        }
        __syncthreads();
        float mu = s_mu[p], is = s_is[p];
        #pragma unroll 8
        for (int j = 0; j < 32; j++) {
            int c = part*32 + j;
            g_yn[base + (size_t)c*NPIX] = __float2bfloat16((v[j] - mu)*is*yw[c] + yb[c]);
        }
    }
}

// ---------------- K2: depthwise QKV + sumsq (vectorized) ----------------
__global__ void __launch_bounds__(256) k_qkv(const float* __restrict__ dw)
{
    const int blk = blockIdx.x;          // b*256 + c
    const int c   = blk & 255;
    const int tid = threadIdx.x;
    __shared__ __align__(16) __nv_bfloat16 sx[66*SROW];
    __shared__ __align__(16) __nv_bfloat16 sy[66*SROW];

    // zero both planes (660 float4 each)
    for (int i = tid; i < 1320; i += 256) {
        if (i < 660) *((float4*)sx + i) = make_float4(0,0,0,0);
        else         *((float4*)sy + (i - 660)) = make_float4(0,0,0,0);
    }
    __syncthreads();
    const size_t pbase = (size_t)blk * NPIX;
    #pragma unroll
    for (int g = 0; g < 2; g++) {
        int gi = g*256 + tid;              // 0..511
        int r = gi >> 3, w = (gi & 7) * 8;
        *(float4*)&sx[(r+1)*SROW + 8 + w] = *(const float4*)&g_xn[pbase + r*64 + w];
        *(float4*)&sy[(r+1)*SROW + 8 + w] = *(const float4*)&g_yn[pbase + r*64 + w];
    }
    __syncthreads();

    float wq[9], wk[9], wv[9];
    #pragma unroll
    for (int j = 0; j < 9; j++) {
        wq[j] = dw[c*9 + j];
        wk[j] = dw[(256 + c)*9 + j];
        wv[j] = dw[(512 + c)*9 + j];
    }

    float sqq = 0.f, sqk = 0.f;
    #pragma unroll
    for (int g = 0; g < 2; g++) {
        int gi = g*256 + tid;
        int r = gi >> 3, w = (gi & 7) * 8;
        uint4 qo, ko, vo;
        unsigned* qp = &qo.x; unsigned* kp = &ko.x; unsigned* vp = &vo.x;
        float qv[2], kv[2], vv[2];
        #pragma unroll
        for (int i = 0; i < 8; i++) {
            int s0 = r*SROW + 7 + w + i;   // top-left of 3x3 window
            float q = 0.f, k = 0.f, v = 0.f;
            #pragma unroll
            for (int dy = 0; dy < 3; dy++)
                #pragma unroll
                for (int dx = 0; dx < 3; dx++) {
                    float xv = __bfloat162float(sx[s0 + dy*SROW + dx]);
                    float yv = __bfloat162float(sy[s0 + dy*SROW + dx]);
                    int t = dy*3 + dx;
                    q = fmaf(xv, wq[t], q);
                    k = fmaf(yv, wk[t], k);
                    v = fmaf(yv, wv[t], v);
                }
            sqq += q*q; sqk += k*k;
            qv[i & 1] = q; kv[i & 1] = k; vv[i & 1] = v;
            if (i & 1) {
                qp[i >> 1] = packbf2(qv[0], qv[1]);
                kp[i >> 1] = packbf2(kv[0], kv[1]);
                vp[i >> 1] = packbf2(vv[0], vv[1]);
            }
        }
        *(uint4*)&g_q[pbase + r*64 + w] = qo;
        *(uint4*)&g_k[pbase + r*64 + w] = ko;
        *(uint4*)&g_v[pbase + r*64 + w] = vo;
    }
    #pragma unroll
    for (int off = 16; off; off >>= 1) {
        sqq += __shfl_down_sync(0xffffffffu, sqq, off);
        sqk += __shfl_down_sync(0xffffffffu, sqk, off);
    }
    __shared__ float rq[8], rk[8];
    if ((tid & 31) == 0) { rq[tid >> 5] = sqq; rk[tid >> 5] = sqk; }
    __syncthreads();
    if (tid == 0) {
        float a = 0.f, bqv = 0.f;
        #pragma unroll
        for (int j = 0; j < 8; j++) { a += rq[j]; bqv += rk[j]; }
        g_sumsq_q[blk] = a;
        g_sumsq_k[blk] = bqv;
    }
}

// ---------------- K3: QK^T partials (split-K=8, mma) ----------------
__global__ void __launch_bounds__(256) k_qks()
{
    const int seg = blockIdx.x;   // 0..7  (512 pixels each)
    const int bh  = blockIdx.y;   // 0..63
    const int b = bh >> 3, h = bh & 7;
    const int tid = threadIdx.x, lane = tid & 31, warp = tid >> 5;
    const int gid = lane >> 2, tg = lane & 3;

    __shared__ __align__(16) char smraw[2*2*32*136*2];
    __nv_bfloat16* sQ = (__nv_bfloat16*)smraw;
    __nv_bfloat16* sK = sQ + 2*32*136;
    float* stage = (float*)smraw;
    const unsigned sQu = (unsigned)__cvta_generic_to_shared(sQ);
    const unsigned sKu = (unsigned)__cvta_generic_to_shared(sK);

    const size_t base = ((size_t)b*C_ + h*32) * NPIX;
    const int r  = tid >> 3;
    const int cg = (tid & 7) * 16;

    auto prefetch = [&](int c, int buf) {
        const int n0 = seg*512 + c * 128;
        const __nv_bfloat16* qp = g_q + base + (size_t)r*NPIX + n0 + cg;
        const __nv_bfloat16* kp = g_k + base + (size_t)r*NPIX + n0 + cg;
        unsigned dq = sQu + (buf*32*136 + r*136 + cg) * 2;
        unsigned dk = sKu + (buf*32*136 + r*136 + cg) * 2;
        CP16(dq,      qp);
        CP16(dq + 16, qp + 8);
        CP16(dk,      kp);
        CP16(dk + 16, kp + 8);
        asm volatile("cp.async.commit_group;" ::);
    };

    float acc[2][4][4];
    #pragma unroll
    for (int i = 0; i < 2; i++)
        #pragma unroll
        for (int j = 0; j < 4; j++)
            #pragma unroll
            for (int q = 0; q < 4; q++) acc[i][j][q] = 0.f;

    prefetch(0, 0);

    for (int c = 0; c < 4; c++) {
        const int buf = c & 1;
        if (c + 1 < 4) {
            prefetch(c + 1, buf ^ 1);
            asm volatile("cp.async.wait_group 1;" ::);
        } else {
            asm volatile("cp.async.wait_group 0;" ::);
        }
        __syncthreads();

        const int col = warp*16 + (lane >> 4)*8;
        unsigned a[2][4];
        #pragma unroll
        for (int mt = 0; mt < 2; mt++) {
            unsigned addr = sQu + (buf*32*136 + (mt*16 + (lane & 15))*136 + col) * 2;
            LDSM4(a[mt][0], a[mt][1], a[mt][2], a[mt][3], addr);
        }
        #pragma unroll
        for (int nt = 0; nt < 2; nt++) {
            unsigned r0, r1, r2, r3;
            unsigned addr = sKu + (buf*32*136 + (nt*16 + (lane & 15))*136 + col) * 2;
            LDSM4(r0, r1, r2, r3, addr);
            MMA16816(acc[0][nt*2],   a[0], r0, r2);
            MMA16816(acc[1][nt*2],   a[1], r0, r2);
            MMA16816(acc[0][nt*2+1], a[0], r1, r3);
            MMA16816(acc[1][nt*2+1], a[1], r1, r3);
        }
        __syncthreads();
    }

    #pragma unroll
    for (int mt = 0; mt < 2; mt++)
        #pragma unroll
        for (int j = 0; j < 4; j++) {
            int c0 = mt*16 + gid, d0 = j*8 + tg*2;
            stage[warp*1056 + c0*33 + d0]       = acc[mt][j][0];
            stage[warp*1056 + c0*33 + d0 + 1]   = acc[mt][j][1];
            stage[warp*1056 + (c0+8)*33 + d0]   = acc[mt][j][2];
            stage[warp*1056 + (c0+8)*33 + d0+1] = acc[mt][j][3];
        }
    __syncthreads();

    const int cc = tid >> 3;
    const int dg = (tid & 7) * 4;
    float4 v = make_float4(0.f, 0.f, 0.f, 0.f);
    #pragma unroll
    for (int w = 0; w < 8; w++) {
        const float* sp = &stage[w*1056 + cc*33 + dg];
        v.x += sp[0]; v.y += sp[1]; v.z += sp[2]; v.w += sp[3];
    }
    *(float4*)&g_part[(((size_t)seg*64 + bh)*32 + cc)*32 + dg] = v;
}

// ---------------- K4: reduce partials + scale + softmax ----------------
__global__ void __launch_bounds__(256) k_soft(const float* __restrict__ temp)
{
    const int bh = blockIdx.x;
    const int b = bh >> 3, h = bh & 7;
    const int tid = threadIdx.x;
    const int cc = tid >> 3;
    const int dg = (tid & 7) * 4;
    const float t = temp[h];

    float v[4] = {0.f, 0.f, 0.f, 0.f};
    #pragma unroll
    for (int sg = 0; sg < 8; sg++) {
        float4 l = *(const float4*)&g_part[(((size_t)sg*64 + bh)*32 + cc)*32 + dg];
        v[0] += l.x; v[1] += l.y; v[2] += l.z; v[3] += l.w;
    }
    float nq = sqrtf(g_sumsq_q[b*C_ + h*32 + cc]);
    float rq = 1.f / fmaxf(nq, 1e-12f);
    float mx = -1e30f;
    #pragma unroll
    for (int j = 0; j < 4; j++) {
        float nk = sqrtf(g_sumsq_k[b*C_ + h*32 + dg + j]);
        v[j] *= rq * (1.f / fmaxf(nk, 1e-12f)) * t;
        mx = fmaxf(mx, v[j]);
    }
    #pragma unroll
    for (int m = 1; m < 8; m <<= 1) mx = fmaxf(mx, __shfl_xor_sync(0xffffffffu, mx, m));
    float sum = 0.f;
    #pragma unroll
    for (int j = 0; j < 4; j++) { v[j] = expf(v[j] - mx); sum += v[j]; }
    #pragma unroll
    for (int m = 1; m < 8; m <<= 1) sum += __shfl_xor_sync(0xffffffffu, sum, m);
    float inv = 1.f / sum;
    __nv_bfloat162* op = reinterpret_cast<__nv_bfloat162*>(&g_attnb[(size_t)bh*1024 + cc*32 + dg]);
    op[0] = __floats2bfloat162_rn(v[0]*inv, v[1]*inv);
    op[1] = __floats2bfloat162_rn(v[2]*inv, v[3]*inv);
}

// ---------------- K5: out = attn @ v (mma) ----------------
__global__ void __launch_bounds__(256) k_av2()
{
    const int seg = blockIdx.x;
    const int bh  = blockIdx.y;
    const int b = bh >> 3, h = bh & 7;
    const int tid = threadIdx.x, lane = tid & 31, warp = tid >> 5;
    const int gid = lane >> 2, tg = lane & 3;

    __shared__ __align__(16) __nv_bfloat16 sA[32*40];
    __shared__ __align__(16) __nv_bfloat16 sV[32*520];
    const unsigned sAu = (unsigned)__cvta_generic_to_shared(&sA[0]);
    const unsigned sVu = (unsigned)__cvta_generic_to_shared(&sV[0]);

    {
        int c0 = tid >> 3, d0 = (tid & 7) * 4;
        const __nv_bfloat162* ap = reinterpret_cast<const __nv_bfloat162*>(
            &g_attnb[(size_t)bh*1024 + c0*32 + d0]);
        __nv_bfloat162* sp = reinterpret_cast<__nv_bfloat162*>(&sA[c0*40 + d0]);
        sp[0] = ap[0]; sp[1] = ap[1];
    }
    const size_t vbase = ((size_t)b*C_ + h*32) * NPIX;
    const int pb0 = seg * 512;
    {
        int r = tid >> 3, cg = (tid & 7) * 64;
        #pragma unroll
        for (int j = 0; j < 8; j++)
            *(float4*)&sV[r*520 + cg + j*8] =
                *(const float4*)&g_v[vbase + (size_t)r*NPIX + pb0 + cg + j*8];
    }
    __syncthreads();

    float acc[2][8][4];
    #pragma unroll
    for (int i = 0; i < 2; i++)
        #pragma unroll
        for (int j = 0; j < 8; j++)
            #pragma unroll
            for (int q = 0; q < 4; q++) acc[i][j][q] = 0.f;

    #pragma unroll
    for (int kt = 0; kt < 2; kt++) {
        unsigned a[2][4];
        #pragma unroll
        for (int mt = 0; mt < 2; mt++) {
            unsigned addr = sAu + ((mt*16 + (lane & 15))*40 + kt*16 + (lane >> 4)*8) * 2;
            LDSM4(a[mt][0], a[mt][1], a[mt][2], a[mt][3], addr);
        }
        #pragma unroll
        for (int ntp = 0; ntp < 4; ntp++) {
            unsigned b0, b1, b2, b3;
            unsigned addr = sVu + ((kt*16 + (lane & 7) + ((lane >> 3) & 1)*8)*520 +
                warp*64 + ntp*16 + (lane >> 4)*8) * 2;
            LDSM4T(b0, b1, b2, b3, addr);
            MMA16816(acc[0][2*ntp],   a[0], b0, b1);
            MMA16816(acc[1][2*ntp],   a[1], b0, b1);
            MMA16816(acc[0][2*ntp+1], a[0], b2, b3);
            MMA16816(acc[1][2*ntp+1], a[1], b2, b3);
        }
    }

    #pragma unroll
    for (int mt = 0; mt < 2; mt++)
        #pragma unroll
        for (int nt = 0; nt < 8; nt++) {
            int row = mt*16 + gid;
            int col = pb0 + warp*64 + nt*8 + tg*2;
            size_t o0 = vbase + (size_t)row*NPIX + col;
            size_t o1 = o0 + (size_t)8*NPIX;
            *(__nv_bfloat162*)&g_ov[o0] = __floats2bfloat162_rn(acc[mt][nt][0], acc[mt][nt][1]);
            *(__nv_bfloat162*)&g_ov[o1] = __floats2bfloat162_rn(acc[mt][nt][2], acc[mt][nt][3]);
        }
}

// ---------------- K6: LN2 -> bf16 into g_xn (register-cached) ----------------
__global__ void __launch_bounds__(256) k_ln2(const float* __restrict__ w,
                                             const float* __restrict__ bia)
{
    const int blk = blockIdx.x;
    const int b  = blk >> 7;
    const int pt = (blk & 127) * 32;
    const int tid = threadIdx.x;
    const int p = tid & 31;
    const int part = tid >> 5;
    const size_t base = (size_t)b*C_*NPIX + pt + p;

    __shared__ float ss[8][32], qq[8][32], s_mu[32], s_is[32];
    float v[32];
    float s = 0.f, sq = 0.f;
    #pragma unroll 8
    for (int j = 0; j < 32; j++) {
        v[j] = g_x1[base + (size_t)(part*32 + j)*NPIX];
        s += v[j]; sq += v[j]*v[j];
    }
    ss[part][p] = s; qq[part][p] = sq;
    __syncthreads();
    if (tid < 32) {
        float a = 0.f, c2 = 0.f;
        #pragma unroll
        for (int j = 0; j < 8; j++) { a += ss[j][tid]; c2 += qq[j][tid]; }
        float mu = a * (1.f/256.f);
        float var = c2 * (1.f/256.f) - mu*mu;
        s_mu[tid] = mu; s_is[tid] = rsqrtf(var + 1e-5f);
    }
    __syncthreads();
    float mu = s_mu[p], is = s_is[p];
    #pragma unroll 8
    for (int j = 0; j < 32; j++) {
        int c = part*32 + j;
        g_xn[base + (size_t)c*NPIX] = __float2bfloat16((v[j] - mu)*is*w[c] + bia[c]);
    }
}

// ---------------- tensor-core GEMM (1x1 convs), 4-stage pipeline ----------------
template<int MODE>
__global__ void __launch_bounds__(256) k_mma(const __nv_bfloat16* __restrict__ Wb,
                                             const __nv_bfloat16* __restrict__ Act,
                                             const float* __restrict__ res,
                                             float* __restrict__ outp)
{
    constexpr int O = (MODE == 1) ? 1360 : 256;
    constexpr int K = (MODE == 2) ? 680 : 256;
    constexpr int NC = (K + 31) / 32;
    constexpr int ASZ = 128*40;
    constexpr int BSZ = 32*136;

    const int b  = blockIdx.z;
    const int bn = blockIdx.x * 128;
    const int bm = blockIdx.y * 128;
    const int tid = threadIdx.x, lane = tid & 31, warp = tid >> 5;
    const int wm = warp >> 1, wn = warp & 1;
    const int gid = lane >> 2, tg = lane & 3;

    __shared__ __align__(16) __nv_bfloat16 sA[4][ASZ];
    __shared__ __align__(16) __nv_bfloat16 sB[4][BSZ];
    const unsigned sAu = (unsigned)__cvta_generic_to_shared(&sA[0][0]);
    const unsigned sBu = (unsigned)__cvta_generic_to_shared(&sB[0][0]);

    const int ar = tid >> 1, ac = (tid & 1) * 16;
    const int bk = tid >> 3, bn8 = (tid & 7) * 16;
    int arow = bm + ar; if (arow > O-1) arow = O-1;
    const __nv_bfloat16* Arow = Wb + (size_t)arow * K;
    const __nv_bfloat16* Bbase = Act + (size_t)b * K * NPIX + bn;

    float acc[2][8][4];
    #pragma unroll
    for (int i = 0; i < 2; i++)
        #pragma unroll
        for (int j = 0; j < 8; j++)
            #pragma unroll
            for (int q = 0; q < 4; q++) acc[i][j][q] = 0.f;

    auto load_chunk = [&](int c, int buf) {
        const int k0 = c * 32;
        #pragma unroll
        for (int j = 0; j < 2; j++) {
            int ko = ac + j*8;
            unsigned dst = sAu + (buf*ASZ + ar*40 + ko) * 2;
            if (k0 + ko < K) { CP16(dst, Arow + k0 + ko); }
            else *(float4*)(&sA[buf][ar*40 + ko]) = make_float4(0,0,0,0);
        }
        #pragma unroll
        for (int j = 0; j < 2; j++) {
            int no = bn8 + j*8;
            unsigned dst = sBu + (buf*BSZ + bk*136 + no) * 2;
            if (k0 + bk < K) { CP16(dst, Bbase + (size_t)(k0 + bk)*NPIX + no); }
            else *(float4*)(&sB[buf][bk*136 + no]) = make_float4(0,0,0,0);
        }
        asm volatile("cp.async.commit_group;" ::);
    };

    load_chunk(0, 0);
    load_chunk(1, 1);
    load_chunk(2, 2);

    for (int c = 0; c < NC; c++) {
        const int buf = c & 3;
        const int rem = NC - 1 - c;
        if (rem >= 2)      { asm volatile("cp.async.wait_group 2;" ::); }
        else if (rem == 1) { asm volatile("cp.async.wait_group 1;" ::); }
        else               { asm volatile("cp.async.wait_group 0;" ::); }
        __syncthreads();
        if (c + 3 < NC) load_chunk(c + 3, (c + 3) & 3);

        #pragma unroll
        for (int kt = 0; kt < 2; kt++) {
            unsigned a[2][4];
            #pragma unroll
            for (int mt = 0; mt < 2; mt++) {
                unsigned addr = sAu + (buf*ASZ +
                    (wm*32 + mt*16 + (lane & 15))*40 + kt*16 + (lane >> 4)*8) * 2;
                LDSM4(a[mt][0], a[mt][1], a[mt][2], a[mt][3], addr);
            }
            #pragma unroll
            for (int ntp = 0; ntp < 4; ntp++) {
                unsigned b0, b1, b2, b3;
                unsigned addr = sBu + (buf*BSZ +
                    (kt*16 + (lane & 7) + ((lane >> 3) & 1)*8)*136 +
                    wn*64 + ntp*16 + (lane >> 4)*8) * 2;
                LDSM4T(b0, b1, b2, b3, addr);
                MMA16816(acc[0][2*ntp],   a[0], b0, b1);
                MMA16816(acc[1][2*ntp],   a[1], b0, b1);
                MMA16816(acc[0][2*ntp+1], a[0], b2, b3);
                MMA16816(acc[1][2*ntp+1], a[1], b2, b3);
            }
        }
    }

    #pragma unroll
    for (int mt = 0; mt < 2; mt++) {
        #pragma unroll
        for (int nt = 0; nt < 8; nt++) {
            int row = bm + wm*32 + mt*16 + gid;
            int col = bn + wn*64 + nt*8 + tg*2;
            float* a4 = acc[mt][nt];
            if (MODE == 0) {
                size_t o0 = ((size_t)b*256 + row)*NPIX + col;
                size_t o1 = o0 + (size_t)8*NPIX;
                float2 r0 = *(const float2*)&res[o0];
                float2 r1 = *(const float2*)&res[o1];
                *(float2*)&g_x1[o0] = make_float2(r0.x + a4[0], r0.y + a4[1]);
                *(float2*)&g_x1[o1] = make_float2(r1.x + a4[2], r1.y + a4[3]);
            } else if (MODE == 1) {
                if (row < 1360) {
                    size_t o0 = ((size_t)b*1360 + row)*NPIX + col;
                    *(__nv_bfloat162*)&g_t[o0] = __floats2bfloat162_rn(a4[0], a4[1]);
                }
                if (row + 8 < 1360) {
                    size_t o1 = ((size_t)b*1360 + row + 8)*NPIX + col;
                    *(__nv_bfloat162*)&g_t[o1] = __floats2bfloat162_rn(a4[2], a4[3]);
                }
            } else {
                size_t o0 = ((size_t)b*256 + row)*NPIX + col;
                size_t o1 = o0 + (size_t)8*NPIX;
                float2 r0 = *(const float2*)&g_x1[o0];
                float2 r1 = *(const float2*)&g_x1[o1];
                *(float2*)&outp[o0] = make_float2(r0.x + a4[0], r0.y + a4[1]);
                *(float2*)&outp[o1] = make_float2(r1.x + a4[2], r1.y + a4[3]);
            }
        }
    }
}

// ---------------- K8: depthwise + GELU gate (vectorized) ----------------
__global__ void __launch_bounds__(256) k_gate(const float* __restrict__ dw)
{
    const int blk = blockIdx.x;         // b*680 + i
    const int b = blk / HID_, i = blk % HID_;
    const int tid = threadIdx.x;
    __shared__ __align__(16) __nv_bfloat16 s1[66*SROW];
    __shared__ __align__(16) __nv_bfloat16 s2[66*SROW];

    for (int j = tid; j < 1320; j += 256) {
        if (j < 660) *((float4*)s1 + j) = make_float4(0,0,0,0);
        else         *((float4*)s2 + (j - 660)) = make_float4(0,0,0,0);
    }
    __syncthreads();
    const size_t base1 = ((size_t)b*2*HID_ + i) * NPIX;
    const size_t base2 = ((size_t)b*2*HID_ + HID_ + i) * NPIX;
    #pragma unroll
    for (int g = 0; g < 2; g++) {
        int gi = g*256 + tid;
        int r = gi >> 3, w = (gi & 7) * 8;
        *(float4*)&s1[(r+1)*SROW + 8 + w] = *(const float4*)&g_t[base1 + r*64 + w];
        *(float4*)&s2[(r+1)*SROW + 8 + w] = *(const float4*)&g_t[base2 + r*64 + w];
    }
    __syncthreads();

    float w1[9], w2[9];
    #pragma unroll
    for (int j = 0; j < 9; j++) {
        w1[j] = dw[i*9 + j];
        w2[j] = dw[(HID_ + i)*9 + j];
    }
    const size_t obase = ((size_t)b*HID_ + i) * NPIX;
    #pragma unroll
    for (int g = 0; g < 2; g++) {
        int gi = g*256 + tid;
        int r = gi >> 3, w = (gi & 7) * 8;
        uint4 ho;
        unsigned* hp = &ho.x;
        float hv[2];
        #pragma unroll
        for (int px = 0; px < 8; px++) {
            int s0 = r*SROW + 7 + w + px;
            float a = 0.f, gg = 0.f;
            #pragma unroll
            for (int dy = 0; dy < 3; dy++)
                #pragma unroll
                for (int dx = 0; dx < 3; dx++) {
                    int t = dy*3 + dx;
                    a  = fmaf(__bfloat162float(s1[s0 + dy*SROW + dx]), w1[t], a);
                    gg = fmaf(__bfloat162float(s2[s0 + dy*SROW + dx]), w2[t], gg);
                }
            float ge = 0.5f * a * (1.f + erff(a * 0.70710678118654752f));
            hv[px & 1] = ge * gg;
            if (px & 1) hp[px >> 1] = packbf2(hv[0], hv[1]);
        }
        *(uint4*)&g_h[obase + r*64 + w] = ho;
    }
}

// ---------------- launch ----------------
extern "C" void kernel_launch(void* const* d_in, const int* in_sizes, int n_in,
                              void* d_out, int out_size)
{
    const float* x        = (const float*)d_in[0];
    const float* y        = (const float*)d_in[1];
    const float* ln1x_w   = (const float*)d_in[2];
    const float* ln1x_b   = (const float*)d_in[3];
    const float* ln1y_w   = (const float*)d_in[4];
    const float* ln1y_b   = (const float*)d_in[5];
    const float* ln2_w    = (const float*)d_in[6];
    const float* ln2_b    = (const float*)d_in[7];
    const float* temp     = (const float*)d_in[8];
    const float* qkv_dw   = (const float*)d_in[9];
    const float* proj_w   = (const float*)d_in[10];
    const float* ffn_in_w = (const float*)d_in[11];
    const float* ffn_dw   = (const float*)d_in[12];
    const float* ffn_out_w= (const float*)d_in[13];
    float* out = (float*)d_out;

    __nv_bfloat16 *wP, *wI, *wO;
    cudaGetSymbolAddress((void**)&wP, g_wP);
    cudaGetSymbolAddress((void**)&wI, g_wI);
    cudaGetSymbolAddress((void**)&wO, g_wO);
    __nv_bfloat16 *ov, *xn, *hh;
    cudaGetSymbolAddress((void**)&ov, g_ov);
    cudaGetSymbolAddress((void**)&xn, g_xn);
    cudaGetSymbolAddress((void**)&hh, g_h);

    k_cvtw<<<576, 256>>>(proj_w, ffn_in_w, ffn_out_w);
    k_ln1<<<B_*128, 256>>>(x, y, ln1x_w, ln1x_b, ln1y_w, ln1y_b);
    k_qkv<<<B_*C_, 256>>>(qkv_dw);
    k_qks<<<dim3(8, 64), 256>>>();
    k_soft<<<64, 256>>>(temp);
    k_av2<<<dim3(8, 64), 256>>>();
    k_mma<0><<<dim3(32, 2, B_), 256>>>(wP, ov, x, nullptr);
    k_ln2<<<B_*128, 256>>>(ln2_w, ln2_b);
    k_mma<1><<<dim3(32, 11, B_), 256>>>(wI, xn, nullptr, nullptr);
    k_gate<<<B_*HID_, 256>>>(ffn_dw);
    k_mma<2><<<dim3(32, 2, B_), 256>>>(wO, hh, nullptr, out);
}